// round 9
// baseline (speedup 1.0000x reference)
#include <cuda_runtime.h>
#include <cuda_bf16.h>
#include <math.h>

#define BB    8
#define TENC  512
#define DIN   512
#define TDEC  150
#define ODIM  80
#define DRNN  1024
#define PRE   256
#define ATTN  128
#define LOC   32
#define KF    31
#define NBLK  148

// ---------------- device scratch ----------------
__device__ __align__(16) float g_pm[BB * TENC * ATTN];
__device__ __align__(16) float g_e[BB * TENC];
__device__ __align__(16) float g_attcum[BB * TENC];
__device__ __align__(16) float g_attc[BB * TDEC * DIN];
__device__ __align__(16) float g_p2[BB * TDEC * PRE];
__device__ __align__(16) float g_h0[2][BB * DRNN];
__device__ __align__(16) float g_c0[2][BB * DRNN];
__device__ __align__(16) float g_h1[2][BB * DRNN];
__device__ __align__(16) float g_c1[2][BB * DRNN];

__device__ unsigned g_bar_count = 0;
__device__ unsigned g_bar_gen = 0;

// ---------------- helpers ----------------
__device__ __forceinline__ float warp_sum(float v) {
    #pragma unroll
    for (int o = 16; o; o >>= 1) v += __shfl_down_sync(0xffffffffu, v, o);
    return v;
}
__device__ __forceinline__ float sigm(float x) { return 1.0f / (1.0f + __expf(-x)); }
__device__ __forceinline__ float tanh_f(float x) {
    float xc = fminf(fmaxf(x, -10.0f), 10.0f);
    float e = __expf(2.0f * xc);
    return __fdividef(e - 1.0f, e + 1.0f);
}
__device__ __forceinline__ float tanh_hw(float x) {
    float y;
    asm("tanh.approx.f32 %0, %1;" : "=f"(y) : "f"(x));
    return y;
}

// grid-wide barrier (all NBLK blocks resident: 148 blocks, 1/SM)
__device__ __forceinline__ void gsync() {
    __syncthreads();
    if (threadIdx.x == 0) {
        __threadfence();
        unsigned gen = *((volatile unsigned*)&g_bar_gen);
        if (atomicAdd(&g_bar_count, 1u) == NBLK - 1) {
            atomicExch(&g_bar_count, 0u);
            __threadfence();
            atomicExch(&g_bar_gen, gen + 1u);
        } else {
            while (*((volatile unsigned*)&g_bar_gen) == gen) {}
        }
    }
    __syncthreads();
}

// ---------------- init ----------------
__global__ void init_kernel() {
    int i = blockIdx.x * 256 + threadIdx.x;
    if (i < BB * DRNN) {
        g_h0[0][i] = 0.f; g_h0[1][i] = 0.f;
        g_c0[0][i] = 0.f; g_c0[1][i] = 0.f;
        g_h1[0][i] = 0.f; g_h1[1][i] = 0.f;
        g_c1[0][i] = 0.f; g_c1[1][i] = 0.f;
    }
    if (i < BB * TENC) g_attcum[i] = 0.f;
}

// ---------------- processed memory ----------------
__global__ __launch_bounds__(256) void pm_kernel(const float* __restrict__ mem,
                                                 const float* __restrict__ Wmem) {
    int b = blockIdx.x >> 6;
    int t0 = (blockIdx.x & 63) * 8;
    __shared__ __align__(16) float smb[8 * DIN];
    const float* mptr = mem + ((size_t)b * TENC + t0) * DIN;
    for (int i = threadIdx.x; i < 8 * DIN; i += 256) smb[i] = mptr[i];
    __syncthreads();
    int w = threadIdx.x >> 5, ln = threadIdx.x & 31;
    for (int ai = 0; ai < 16; ai++) {
        int a = w * 16 + ai;
        const float4* wr = (const float4*)(Wmem + (size_t)a * DIN);
        float acc[8] = {0,0,0,0,0,0,0,0};
        #pragma unroll
        for (int it = 0; it < 4; it++) {
            float4 wv = wr[ln + it * 32];
            #pragma unroll
            for (int t = 0; t < 8; t++) {
                float4 hv = *(const float4*)(smb + t * DIN + (ln + it * 32) * 4);
                acc[t] += wv.x*hv.x + wv.y*hv.y + wv.z*hv.z + wv.w*hv.w;
            }
        }
        #pragma unroll
        for (int t = 0; t < 8; t++) {
            float v = warp_sum(acc[t]);
            if (ln == 0) g_pm[((size_t)(b * TENC) + (t0 + t)) * ATTN + a] = v;
        }
    }
}

// ---------------- prenet ----------------
__global__ __launch_bounds__(256) void prenet_kernel(const float* __restrict__ tgt,
        const float* __restrict__ W1, const float* __restrict__ b1,
        const float* __restrict__ W2, const float* __restrict__ b2) {
    int b = blockIdx.x / TDEC, s = blockIdx.x % TDEC;
    __shared__ float prev[80];
    __shared__ float p1s[PRE];
    int tid = threadIdx.x;
    if (tid < 80) prev[tid] = (s == 0) ? 0.f : tgt[((size_t)b * TDEC + (s - 1)) * ODIM + tid];
    __syncthreads();
    int w = tid >> 5, ln = tid & 31;
    for (int oi = 0; oi < 32; oi++) {
        int o = w * 32 + oi;
        float acc = 0.f;
        int k = ln * 4;
        if (k < 80) {
            float4 wv = *(const float4*)(W1 + (size_t)o * 80 + k);
            acc = wv.x*prev[k] + wv.y*prev[k+1] + wv.z*prev[k+2] + wv.w*prev[k+3];
        }
        acc = warp_sum(acc);
        if (ln == 0) p1s[o] = fmaxf(acc + b1[o], 0.f);
    }
    __syncthreads();
    for (int oi = 0; oi < 32; oi++) {
        int o = w * 32 + oi;
        float acc = 0.f;
        #pragma unroll
        for (int it = 0; it < 2; it++) {
            int k = ln * 4 + it * 128;
            float4 wv = *(const float4*)(W2 + (size_t)o * PRE + k);
            acc += wv.x*p1s[k] + wv.y*p1s[k+1] + wv.z*p1s[k+2] + wv.w*p1s[k+3];
        }
        acc = warp_sum(acc);
        if (ln == 0) g_p2[((size_t)b * TDEC + s) * PRE + o] = fmaxf(acc + b2[o], 0.f);
    }
}

// ---------------- out/stop projection (warp per (col,b)) ----------------
__device__ __forceinline__ void outstop_warp(int col, int b, int sprev, int h1buf, int ln,
        const float* __restrict__ featW, const float* __restrict__ stopW,
        const float* __restrict__ stopb, float* __restrict__ out) {
    const float4* wr = (const float4*)((col < ODIM) ? (featW + (size_t)col * 1536) : stopW);
    const float4* h1p = (const float4*)(g_h1[h1buf] + b * DRNN);
    const float4* acp = (const float4*)(g_attc + ((size_t)(b * TDEC) + sprev) * DIN);
    float acc = 0.f;
    #pragma unroll
    for (int it = 0; it < 8; it++) {
        float4 wv = wr[ln + it * 32];
        float4 zv = h1p[ln + it * 32];
        acc += wv.x*zv.x + wv.y*zv.y + wv.z*zv.z + wv.w*zv.w;
    }
    #pragma unroll
    for (int it = 0; it < 4; it++) {
        float4 wv = wr[256 + ln + it * 32];
        float4 zv = acp[ln + it * 32];
        acc += wv.x*zv.x + wv.y*zv.y + wv.z*zv.z + wv.w*zv.w;
    }
    acc = warp_sum(acc);
    if (ln == 0) {
        if (col < ODIM) out[((size_t)(b * TDEC) + sprev) * ODIM + col] = acc;
        else            out[BB * TDEC * ODIM + b * TDEC + sprev] = acc + stopb[0];
    }
}

// ---------------- persistent decoder ----------------
__global__ __launch_bounds__(256) void decoder_persistent(
        const float* __restrict__ mem, const int* __restrict__ mlen,
        const float* __restrict__ Wq, const float* __restrict__ Wloc,
        const float* __restrict__ filt, const float* __restrict__ av,
        const float* __restrict__ ab,
        const float* __restrict__ Wi0, const float* __restrict__ Wh0,
        const float* __restrict__ bl0,
        const float* __restrict__ Wi1, const float* __restrict__ Wh1,
        const float* __restrict__ bl1,
        const float* __restrict__ featW, const float* __restrict__ stopW,
        const float* __restrict__ stopb, float* __restrict__ out)
{
    extern __shared__ __align__(16) float sm[];
    const int bid = blockIdx.x, tid = threadIdx.x;
    const int w = tid >> 5, ln = tid & 31;

    for (int s = 0; s < TDEC; s++) {
        const int par = s & 1, nxt = par ^ 1;

        // ============ phase A: q + attention energies ============
        if (bid < 128) {
            const int b = bid >> 4, t0 = (bid & 15) * 32;
            float* qs  = sm;            // 128
            float* vv  = sm + 128;      // 128
            float* Wl  = sm + 256;      // 4096 [a*32+c]
            float* fs  = sm + 4352;     // 32*33 [t*33+c]
            float* cum = sm + 5408;     // 64
            float* flt = sm + 5472;     // 992 [c*31+k]
            float* eps = sm + 6464;     // 256
            for (int i = tid; i < 4096; i += 256) Wl[i] = Wloc[i];
            for (int i = tid; i < 992; i += 256) flt[i] = filt[i];
            if (tid < 128) vv[tid] = av[tid];
            if (tid < 64) {
                int t = t0 - 15 + tid;
                cum[tid] = (t >= 0 && t < TENC) ? g_attcum[b * TENC + t] : 0.f;
            }
            // q = h0 @ Wq^T (+ attn_b), warp w -> a in [w*16, w*16+16)
            {
                float4 hv[8];
                const float4* hp = (const float4*)(g_h0[par] + b * DRNN);
                #pragma unroll
                for (int i2 = 0; i2 < 8; i2++) hv[i2] = hp[ln + i2 * 32];
                for (int i2 = 0; i2 < 16; i2++) {
                    int a = w * 16 + i2;
                    const float4* wr = (const float4*)(Wq + (size_t)a * DRNN);
                    float acc = 0.f;
                    #pragma unroll
                    for (int k = 0; k < 8; k++) {
                        float4 wv = wr[ln + k * 32];
                        acc += wv.x*hv[k].x + wv.y*hv[k].y + wv.z*hv[k].z + wv.w*hv[k].w;
                    }
                    acc = warp_sum(acc);
                    if (ln == 0) qs[a] = acc + ab[a];
                }
            }
            __syncthreads();
            // location conv: warp w handles c = w*4..w*4+3, lane = t
            #pragma unroll
            for (int cc = 0; cc < 4; cc++) {
                int c = w * 4 + cc;
                float f = 0.f;
                #pragma unroll
                for (int k = 0; k < KF; k++) f += cum[ln + k] * flt[c * KF + k];
                fs[ln * 33 + c] = f;
            }
            __syncthreads();
            // loc gemm (warp owns 16 a, lanes = t) + energies
            float acc[16];
            #pragma unroll
            for (int i2 = 0; i2 < 16; i2++) acc[i2] = 0.f;
            #pragma unroll 4
            for (int c = 0; c < 32; c++) {
                float fv = fs[ln * 33 + c];
                #pragma unroll
                for (int i2 = 0; i2 < 16; i2++)
                    acc[i2] += fv * Wl[(w * 16 + i2) * 32 + c];
            }
            const float4* pmp = (const float4*)(g_pm + ((size_t)(b * TENC) + t0 + ln) * ATTN + w * 16);
            float ep = 0.f;
            #pragma unroll
            for (int v4 = 0; v4 < 4; v4++) {
                float4 p = pmp[v4];
                int a = w * 16 + v4 * 4;
                ep += vv[a    ] * tanh_hw(p.x + acc[v4*4    ] + qs[a    ]);
                ep += vv[a + 1] * tanh_hw(p.y + acc[v4*4 + 1] + qs[a + 1]);
                ep += vv[a + 2] * tanh_hw(p.z + acc[v4*4 + 2] + qs[a + 2]);
                ep += vv[a + 3] * tanh_hw(p.w + acc[v4*4 + 3] + qs[a + 3]);
            }
            eps[w * 32 + ln] = ep;
            __syncthreads();
            if (w == 0) {
                float e = 0.f;
                #pragma unroll
                for (int ww = 0; ww < 8; ww++) e += eps[ww * 32 + ln];
                g_e[b * TENC + t0 + ln] = e;
            }
        }
        gsync();

        // ============ phase B: softmax + context + attcum + att_w, outstop(s-1) ============
        if (bid < 16) {
            const int b = bid >> 1, half = bid & 1;
            float* wsm = sm;        // 512
            float* red = sm + 512;  // 8
            int len = mlen[b];
            const float* ep = g_e + b * TENC;
            float e0 = (tid       < len) ? ep[tid      ] : -1e9f;
            float e1 = (tid + 256 < len) ? ep[tid + 256] : -1e9f;
            float mx = fmaxf(e0, e1);
            #pragma unroll
            for (int o = 16; o; o >>= 1) mx = fmaxf(mx, __shfl_xor_sync(0xffffffffu, mx, o));
            if (ln == 0) red[w] = mx;
            __syncthreads();
            mx = red[0];
            #pragma unroll
            for (int ww = 1; ww < 8; ww++) mx = fmaxf(mx, red[ww]);
            float x0 = __expf(e0 - mx), x1 = __expf(e1 - mx);
            float sw = warp_sum(x0 + x1);
            __syncthreads();
            if (ln == 0) red[w] = sw;
            __syncthreads();
            float S = 0.f;
            #pragma unroll
            for (int ww = 0; ww < 8; ww++) S += red[ww];
            float inv = __fdividef(1.0f, S);
            wsm[tid      ] = x0 * inv;
            wsm[tid + 256] = x1 * inv;
            __syncthreads();
            // context over 256-wide d-tile
            int d = half * 256 + tid;
            const float* mp = mem + ((size_t)b * TENC) * DIN + d;
            float a0 = 0.f, a1 = 0.f, a2 = 0.f, a3 = 0.f;
            #pragma unroll 2
            for (int t = 0; t < TENC; t += 4) {
                a0 += wsm[t    ] * mp[(size_t)(t    ) * DIN];
                a1 += wsm[t + 1] * mp[(size_t)(t + 1) * DIN];
                a2 += wsm[t + 2] * mp[(size_t)(t + 2) * DIN];
                a3 += wsm[t + 3] * mp[(size_t)(t + 3) * DIN];
            }
            g_attc[((size_t)(b * TDEC) + s) * DIN + d] = (a0 + a1) + (a2 + a3);
            if (half == 0) {
                #pragma unroll
                for (int r = 0; r < 2; r++) {
                    int t = tid + r * 256;
                    float wv = wsm[t];
                    out[BB * TDEC * ODIM + BB * TDEC + ((size_t)(b * TDEC) + s) * TENC + t] = wv;
                    g_attcum[b * TENC + t] += wv;
                }
            }
        } else if (bid >= 16 && bid < 97) {
            if (s > 0) {
                int u = (bid - 16) * 8 + w;
                if (u < (ODIM + 1) * BB)
                    outstop_warp(u >> 3, u & 7, s - 1, par, ln, featW, stopW, stopb, out);
            }
        }
        gsync();

        // ============ phase C: LSTM0 + zoneout ============
        if (bid < 128) {
            float* xs = sm;  // 8*1792
            for (int i = tid; i < 8 * 1792; i += 256) {
                int b = i / 1792, o = i - b * 1792; float v;
                if (o < 512)      v = g_attc[((size_t)(b * TDEC) + s) * DIN + o];
                else if (o < 768) v = g_p2[((size_t)(b * TDEC) + s) * PRE + (o - 512)];
                else              v = g_h0[par][b * DRNN + (o - 768)];
                xs[i] = v;
            }
            __syncthreads();
            int j = bid * 8 + w;
            float acc[4][8];
            #pragma unroll
            for (int g = 0; g < 4; g++)
                #pragma unroll
                for (int b = 0; b < 8; b++) acc[g][b] = 0.f;
            const float4* W0 = (const float4*)Wi0;
            for (int it = 0; it < 6; it++) {
                int kc = ln + it * 32;
                float4 wv[4];
                #pragma unroll
                for (int g = 0; g < 4; g++) wv[g] = W0[(size_t)(g * 1024 + j) * 192 + kc];
                #pragma unroll
                for (int b = 0; b < 8; b++) {
                    float4 xv = *(const float4*)(xs + b * 1792 + kc * 4);
                    #pragma unroll
                    for (int g = 0; g < 4; g++)
                        acc[g][b] += wv[g].x*xv.x + wv[g].y*xv.y + wv[g].z*xv.z + wv[g].w*xv.w;
                }
            }
            const float4* W1 = (const float4*)Wh0;
            for (int it = 0; it < 8; it++) {
                int kc = ln + it * 32;
                float4 wv[4];
                #pragma unroll
                for (int g = 0; g < 4; g++) wv[g] = W1[(size_t)(g * 1024 + j) * 256 + kc];
                #pragma unroll
                for (int b = 0; b < 8; b++) {
                    float4 xv = *(const float4*)(xs + b * 1792 + 768 + kc * 4);
                    #pragma unroll
                    for (int g = 0; g < 4; g++)
                        acc[g][b] += wv[g].x*xv.x + wv[g].y*xv.y + wv[g].z*xv.z + wv[g].w*xv.w;
                }
            }
            #pragma unroll
            for (int g = 0; g < 4; g++)
                #pragma unroll
                for (int b = 0; b < 8; b++) acc[g][b] = warp_sum(acc[g][b]);
            if (ln == 0) {
                float bi = bl0[j], bf = bl0[j + 1024], bg = bl0[j + 2048], bo = bl0[j + 3072];
                #pragma unroll
                for (int b = 0; b < 8; b++) {
                    int idx = b * DRNN + j;
                    float co = g_c0[par][idx], ho = g_h0[par][idx];
                    float cn = sigm(acc[1][b] + bf) * co + sigm(acc[0][b] + bi) * tanh_f(acc[2][b] + bg);
                    float hn = sigm(acc[3][b] + bo) * tanh_f(cn);
                    g_c0[nxt][idx] = 0.9f * cn + 0.1f * co;
                    g_h0[nxt][idx] = 0.9f * hn + 0.1f * ho;
                }
            }
        }
        gsync();

        // ============ phase E: LSTM1 + zoneout ============
        if (bid < 128) {
            float* xs = sm;  // 8*2048
            for (int i = tid; i < 8 * 2048; i += 256) {
                int b = i >> 11, o = i & 2047;
                xs[i] = (o < 1024) ? g_h0[nxt][b * DRNN + o] : g_h1[par][b * DRNN + (o - 1024)];
            }
            __syncthreads();
            int j = bid * 8 + w;
            float acc[4][8];
            #pragma unroll
            for (int g = 0; g < 4; g++)
                #pragma unroll
                for (int b = 0; b < 8; b++) acc[g][b] = 0.f;
            const float4* W0 = (const float4*)Wi1;
            for (int it = 0; it < 8; it++) {
                int kc = ln + it * 32;
                float4 wv[4];
                #pragma unroll
                for (int g = 0; g < 4; g++) wv[g] = W0[(size_t)(g * 1024 + j) * 256 + kc];
                #pragma unroll
                for (int b = 0; b < 8; b++) {
                    float4 xv = *(const float4*)(xs + b * 2048 + kc * 4);
                    #pragma unroll
                    for (int g = 0; g < 4; g++)
                        acc[g][b] += wv[g].x*xv.x + wv[g].y*xv.y + wv[g].z*xv.z + wv[g].w*xv.w;
                }
            }
            const float4* W1 = (const float4*)Wh1;
            for (int it = 0; it < 8; it++) {
                int kc = ln + it * 32;
                float4 wv[4];
                #pragma unroll
                for (int g = 0; g < 4; g++) wv[g] = W1[(size_t)(g * 1024 + j) * 256 + kc];
                #pragma unroll
                for (int b = 0; b < 8; b++) {
                    float4 xv = *(const float4*)(xs + b * 2048 + 1024 + kc * 4);
                    #pragma unroll
                    for (int g = 0; g < 4; g++)
                        acc[g][b] += wv[g].x*xv.x + wv[g].y*xv.y + wv[g].z*xv.z + wv[g].w*xv.w;
                }
            }
            #pragma unroll
            for (int g = 0; g < 4; g++)
                #pragma unroll
                for (int b = 0; b < 8; b++) acc[g][b] = warp_sum(acc[g][b]);
            if (ln == 0) {
                float bi = bl1[j], bf = bl1[j + 1024], bg = bl1[j + 2048], bo = bl1[j + 3072];
                #pragma unroll
                for (int b = 0; b < 8; b++) {
                    int idx = b * DRNN + j;
                    float co = g_c1[par][idx], ho = g_h1[par][idx];
                    float cn = sigm(acc[1][b] + bf) * co + sigm(acc[0][b] + bi) * tanh_f(acc[2][b] + bg);
                    float hn = sigm(acc[3][b] + bo) * tanh_f(cn);
                    g_c1[nxt][idx] = 0.9f * cn + 0.1f * co;
                    g_h1[nxt][idx] = 0.9f * hn + 0.1f * ho;
                }
            }
        }
        gsync();
    }

    // ---- final out/stop for step 149 (h1 in buffer 0 after E(149)) ----
    if (bid >= 16 && bid < 97) {
        int u = (bid - 16) * 8 + w;
        if (u < (ODIM + 1) * BB)
            outstop_warp(u >> 3, u & 7, TDEC - 1, 0, ln, featW, stopW, stopb, out);
    }
}

extern "C" void kernel_launch(void* const* d_in, const int* in_sizes, int n_in,
                              void* d_out, int out_size) {
    const float* mem   = (const float*)d_in[0];
    const int*   mlen  = (const int*)  d_in[1];
    const float* tgt   = (const float*)d_in[2];
    const float* Wmem  = (const float*)d_in[3];
    const float* Wq    = (const float*)d_in[4];
    const float* Wloc  = (const float*)d_in[5];
    const float* filt  = (const float*)d_in[6];
    const float* av    = (const float*)d_in[7];
    const float* ab    = (const float*)d_in[8];
    const float* pW1   = (const float*)d_in[9];
    const float* pb1   = (const float*)d_in[10];
    const float* pW2   = (const float*)d_in[11];
    const float* pb2   = (const float*)d_in[12];
    const float* Wi0   = (const float*)d_in[13];
    const float* Wh0   = (const float*)d_in[14];
    const float* bl0   = (const float*)d_in[15];
    const float* Wi1   = (const float*)d_in[16];
    const float* Wh1   = (const float*)d_in[17];
    const float* bl1   = (const float*)d_in[18];
    const float* featW = (const float*)d_in[19];
    const float* stopW = (const float*)d_in[20];
    const float* stopb = (const float*)d_in[21];
    float* out = (float*)d_out;

    static bool attr_set = false;
    if (!attr_set) {
        cudaFuncSetAttribute(decoder_persistent,
                             cudaFuncAttributeMaxDynamicSharedMemorySize, 8 * 2048 * 4);
        attr_set = true;
    }

    init_kernel<<<32, 256>>>();
    pm_kernel<<<512, 256>>>(mem, Wmem);
    prenet_kernel<<<BB * TDEC, 256>>>(tgt, pW1, pb1, pW2, pb2);
    decoder_persistent<<<NBLK, 256, 8 * 2048 * 4>>>(
        mem, mlen, Wq, Wloc, filt, av, ab,
        Wi0, Wh0, bl0, Wi1, Wh1, bl1, featW, stopW, stopb, out);
}

// round 11
// speedup vs baseline: 1.0208x; 1.0208x over previous
#include <cuda_runtime.h>
#include <cuda_bf16.h>
#include <math.h>

#define BB    8
#define TENC  512
#define DIN   512
#define TDEC  150
#define ODIM  80
#define DRNN  1024
#define PRE   256
#define ATTN  128
#define LOC   32
#define KF    31
#define NBLK  148

// smem float offsets
#define OFF_PART  16384          // 512 floats (gate partials)
#define OFF_ACON  16896          // A-phase constants: Wl 4096 | flt 992 | vv 128
#define SMEM_FLOATS (OFF_ACON + 5216)

// ---------------- device scratch ----------------
__device__ __align__(16) float g_pm[BB * TENC * ATTN];
__device__ __align__(16) float g_e[BB * TENC];
__device__ __align__(16) float g_attcum[BB * TENC];
__device__ __align__(16) float g_attc[BB * TDEC * DIN];
__device__ __align__(16) float g_p2[BB * TDEC * PRE];
__device__ __align__(16) float g_q[BB * ATTN];
__device__ __align__(16) float g_h0[2][BB * DRNN];
__device__ __align__(16) float g_c0[2][BB * DRNN];
__device__ __align__(16) float g_h1[2][BB * DRNN];
__device__ __align__(16) float g_c1[2][BB * DRNN];

__device__ unsigned g_bar_count = 0;
__device__ unsigned g_bar_gen = 0;

// ---------------- helpers ----------------
__device__ __forceinline__ float warp_sum(float v) {
    #pragma unroll
    for (int o = 16; o; o >>= 1) v += __shfl_down_sync(0xffffffffu, v, o);
    return v;
}
__device__ __forceinline__ float sigm(float x) { return 1.0f / (1.0f + __expf(-x)); }
__device__ __forceinline__ float tanh_f(float x) {
    float xc = fminf(fmaxf(x, -10.0f), 10.0f);
    float e = __expf(2.0f * xc);
    return __fdividef(e - 1.0f, e + 1.0f);
}
__device__ __forceinline__ float tanh_hw(float x) {
    float y;
    asm("tanh.approx.f32 %0, %1;" : "=f"(y) : "f"(x));
    return y;
}
// packed dual-fp32 FMA: d = a*b + d (elementwise on the two 32-bit lanes)
__device__ __forceinline__ void fma2(unsigned long long& d, unsigned long long a,
                                     unsigned long long b) {
    asm("fma.rn.f32x2 %0, %1, %2, %0;" : "+l"(d) : "l"(a), "l"(b));
}
__device__ __forceinline__ float unpack_sum(unsigned long long u) {
    union { unsigned long long u; float2 f; } cv; cv.u = u;
    return cv.f.x + cv.f.y;
}

// grid-wide barrier (148 blocks, 1/SM)
__device__ __forceinline__ void gsync() {
    __syncthreads();
    if (threadIdx.x == 0) {
        __threadfence();
        unsigned gen = *((volatile unsigned*)&g_bar_gen);
        if (atomicAdd(&g_bar_count, 1u) == NBLK - 1) {
            atomicExch(&g_bar_count, 0u);
            __threadfence();
            atomicExch(&g_bar_gen, gen + 1u);
        } else {
            while (*((volatile unsigned*)&g_bar_gen) == gen) {}
        }
    }
    __syncthreads();
}

// ---------------- init ----------------
__global__ void init_kernel() {
    int i = blockIdx.x * 256 + threadIdx.x;
    if (i < BB * DRNN) {
        g_h0[0][i] = 0.f; g_h0[1][i] = 0.f;
        g_c0[0][i] = 0.f; g_c0[1][i] = 0.f;
        g_h1[0][i] = 0.f; g_h1[1][i] = 0.f;
        g_c1[0][i] = 0.f; g_c1[1][i] = 0.f;
    }
    if (i < BB * TENC) g_attcum[i] = 0.f;
    if (i < BB * ATTN) g_q[i] = 0.f;
}

// ---------------- processed memory ----------------
__global__ __launch_bounds__(256) void pm_kernel(const float* __restrict__ mem,
                                                 const float* __restrict__ Wmem) {
    int b = blockIdx.x >> 6;
    int t0 = (blockIdx.x & 63) * 8;
    __shared__ __align__(16) float smb[8 * DIN];
    const float* mptr = mem + ((size_t)b * TENC + t0) * DIN;
    for (int i = threadIdx.x; i < 8 * DIN; i += 256) smb[i] = mptr[i];
    __syncthreads();
    int w = threadIdx.x >> 5, ln = threadIdx.x & 31;
    for (int ai = 0; ai < 16; ai++) {
        int a = w * 16 + ai;
        const float4* wr = (const float4*)(Wmem + (size_t)a * DIN);
        float acc[8] = {0,0,0,0,0,0,0,0};
        #pragma unroll
        for (int it = 0; it < 4; it++) {
            float4 wv = wr[ln + it * 32];
            #pragma unroll
            for (int t = 0; t < 8; t++) {
                float4 hv = *(const float4*)(smb + t * DIN + (ln + it * 32) * 4);
                acc[t] += wv.x*hv.x + wv.y*hv.y + wv.z*hv.z + wv.w*hv.w;
            }
        }
        #pragma unroll
        for (int t = 0; t < 8; t++) {
            float v = warp_sum(acc[t]);
            if (ln == 0) g_pm[((size_t)(b * TENC) + (t0 + t)) * ATTN + a] = v;
        }
    }
}

// ---------------- prenet ----------------
__global__ __launch_bounds__(256) void prenet_kernel(const float* __restrict__ tgt,
        const float* __restrict__ W1, const float* __restrict__ b1,
        const float* __restrict__ W2, const float* __restrict__ b2) {
    int b = blockIdx.x / TDEC, s = blockIdx.x % TDEC;
    __shared__ float prev[80];
    __shared__ float p1s[PRE];
    int tid = threadIdx.x;
    if (tid < 80) prev[tid] = (s == 0) ? 0.f : tgt[((size_t)b * TDEC + (s - 1)) * ODIM + tid];
    __syncthreads();
    int w = tid >> 5, ln = tid & 31;
    for (int oi = 0; oi < 32; oi++) {
        int o = w * 32 + oi;
        float acc = 0.f;
        int k = ln * 4;
        if (k < 80) {
            float4 wv = *(const float4*)(W1 + (size_t)o * 80 + k);
            acc = wv.x*prev[k] + wv.y*prev[k+1] + wv.z*prev[k+2] + wv.w*prev[k+3];
        }
        acc = warp_sum(acc);
        if (ln == 0) p1s[o] = fmaxf(acc + b1[o], 0.f);
    }
    __syncthreads();
    for (int oi = 0; oi < 32; oi++) {
        int o = w * 32 + oi;
        float acc = 0.f;
        #pragma unroll
        for (int it = 0; it < 2; it++) {
            int k = ln * 4 + it * 128;
            float4 wv = *(const float4*)(W2 + (size_t)o * PRE + k);
            acc += wv.x*p1s[k] + wv.y*p1s[k+1] + wv.z*p1s[k+2] + wv.w*p1s[k+3];
        }
        acc = warp_sum(acc);
        if (ln == 0) g_p2[((size_t)b * TDEC + s) * PRE + o] = fmaxf(acc + b2[o], 0.f);
    }
}

// ---------------- out/stop projection (warp per (col,b)) ----------------
__device__ __forceinline__ void outstop_warp(int col, int b, int sprev, int h1buf, int ln,
        const float* __restrict__ featW, const float* __restrict__ stopW,
        const float* __restrict__ stopb, float* __restrict__ out) {
    const float4* wr = (const float4*)((col < ODIM) ? (featW + (size_t)col * 1536) : stopW);
    const float4* h1p = (const float4*)(g_h1[h1buf] + b * DRNN);
    const float4* acp = (const float4*)(g_attc + ((size_t)(b * TDEC) + sprev) * DIN);
    float acc = 0.f;
    #pragma unroll
    for (int it = 0; it < 8; it++) {
        float4 wv = wr[ln + it * 32];
        float4 zv = h1p[ln + it * 32];
        acc += wv.x*zv.x + wv.y*zv.y + wv.z*zv.z + wv.w*zv.w;
    }
    #pragma unroll
    for (int it = 0; it < 4; it++) {
        float4 wv = wr[256 + ln + it * 32];
        float4 zv = acp[ln + it * 32];
        acc += wv.x*zv.x + wv.y*zv.y + wv.z*zv.z + wv.w*zv.w;
    }
    acc = warp_sum(acc);
    if (ln == 0) {
        if (col < ODIM) out[((size_t)(b * TDEC) + sprev) * ODIM + col] = acc;
        else            out[BB * TDEC * ODIM + b * TDEC + sprev] = acc + stopb[0];
    }
}

// ---------------- persistent decoder ----------------
__global__ __launch_bounds__(512, 1) void decoder_persistent(
        const float* __restrict__ mem, const int* __restrict__ mlen,
        const float* __restrict__ Wq, const float* __restrict__ Wloc,
        const float* __restrict__ filt, const float* __restrict__ av,
        const float* __restrict__ ab,
        const float* __restrict__ Wi0, const float* __restrict__ Wh0,
        const float* __restrict__ bl0,
        const float* __restrict__ Wi1, const float* __restrict__ Wh1,
        const float* __restrict__ bl1,
        const float* __restrict__ featW, const float* __restrict__ stopW,
        const float* __restrict__ stopb, float* __restrict__ out)
{
    extern __shared__ __align__(16) float sm[];
    const int bid = blockIdx.x, tid = threadIdx.x;
    const int w = tid >> 5, ln = tid & 31;

    // load loop-invariant A-phase constants once
    if (bid < 128) {
        float* Wl  = sm + OFF_ACON;          // [a*32+c]
        float* flt = sm + OFF_ACON + 4096;   // [c*31+k]
        float* vv  = sm + OFF_ACON + 5088;
        for (int i = tid; i < 4096; i += 512) Wl[i] = Wloc[i];
        for (int i = tid; i < 992; i += 512) flt[i] = filt[i];
        if (tid < 128) vv[tid] = av[tid];
    }
    __syncthreads();

    for (int s = 0; s < TDEC; s++) {
        const int par = s & 1, nxt = par ^ 1;

        // ============ phase A: attention energies (q precomputed) ============
        if (bid < 128) {
            const int b = bid >> 4, t0 = (bid & 15) * 32;
            float* qs  = sm;            // 128
            float* fs  = sm + 128;      // 32*33
            float* cum = sm + 1184;     // 64
            float* eps = sm + 1248;     // 512
            const float* Wl  = sm + OFF_ACON;
            const float* flt = sm + OFF_ACON + 4096;
            const float* vv  = sm + OFF_ACON + 5088;
            if (tid < 128) qs[tid] = g_q[b * 128 + tid] + ab[tid];
            if (tid < 64) {
                int t = t0 - 15 + tid;
                cum[tid] = (t >= 0 && t < TENC) ? g_attcum[b * TENC + t] : 0.f;
            }
            __syncthreads();
            // conv: channel c = w and w+16, lane = local t
            #pragma unroll
            for (int half = 0; half < 2; half++) {
                int c = w + half * 16;
                float f = 0.f;
                #pragma unroll
                for (int k = 0; k < KF; k++) f += cum[ln + k] * flt[c * KF + k];
                fs[ln * 33 + c] = f;
            }
            __syncthreads();
            // energies: warp owns 8 a-dims, lane = local t
            float acc[8];
            #pragma unroll
            for (int i = 0; i < 8; i++) acc[i] = 0.f;
            #pragma unroll 4
            for (int c = 0; c < 32; c++) {
                float fv = fs[ln * 33 + c];
                #pragma unroll
                for (int i = 0; i < 8; i++)
                    acc[i] += fv * Wl[(w * 8 + i) * 32 + c];
            }
            const float4* pmp = (const float4*)(g_pm + ((size_t)(b * TENC) + t0 + ln) * ATTN + w * 8);
            float ep = 0.f;
            #pragma unroll
            for (int v4 = 0; v4 < 2; v4++) {
                float4 p = pmp[v4];
                int a = w * 8 + v4 * 4;
                ep += vv[a    ] * tanh_hw(p.x + acc[v4*4    ] + qs[a    ]);
                ep += vv[a + 1] * tanh_hw(p.y + acc[v4*4 + 1] + qs[a + 1]);
                ep += vv[a + 2] * tanh_hw(p.z + acc[v4*4 + 2] + qs[a + 2]);
                ep += vv[a + 3] * tanh_hw(p.w + acc[v4*4 + 3] + qs[a + 3]);
            }
            eps[w * 32 + ln] = ep;
            __syncthreads();
            if (w == 0) {
                float e = 0.f;
                #pragma unroll
                for (int ww = 0; ww < 16; ww++) e += eps[ww * 32 + ln];
                g_e[b * TENC + t0 + ln] = e;
            }
        }
        gsync();

        // ============ phase B: softmax + context + attcum, outstop(s-1) ============
        if (bid < 16) {
            const int b = bid >> 1, half = bid & 1;
            float* wsm  = sm;          // 512
            float* red  = sm + 512;    // 16
            float* ctx2 = sm + 528;    // 512
            int len = mlen[b];
            const float* ep = g_e + b * TENC;
            float e0 = (tid < len) ? ep[tid] : -1e9f;
            float mx = e0;
            #pragma unroll
            for (int o = 16; o; o >>= 1) mx = fmaxf(mx, __shfl_xor_sync(0xffffffffu, mx, o));
            if (ln == 0) red[w] = mx;
            __syncthreads();
            mx = red[0];
            #pragma unroll
            for (int ww = 1; ww < 16; ww++) mx = fmaxf(mx, red[ww]);
            float x0 = __expf(e0 - mx);
            float sw = warp_sum(x0);
            __syncthreads();
            if (ln == 0) red[w] = sw;
            __syncthreads();
            float S = 0.f;
            #pragma unroll
            for (int ww = 0; ww < 16; ww++) S += red[ww];
            float inv = __fdividef(1.0f, S);
            wsm[tid] = x0 * inv;
            __syncthreads();
            int tg = tid >> 8, dl = tid & 255;
            int d = half * 256 + dl;
            const float* mp = mem + ((size_t)b * TENC) * DIN + d;
            float a0 = 0.f, a1 = 0.f;
            #pragma unroll 2
            for (int t = tg * 256; t < tg * 256 + 256; t += 2) {
                a0 += wsm[t    ] * mp[(size_t)(t    ) * DIN];
                a1 += wsm[t + 1] * mp[(size_t)(t + 1) * DIN];
            }
            ctx2[tid] = a0 + a1;
            __syncthreads();
            if (tg == 0)
                g_attc[((size_t)(b * TDEC) + s) * DIN + d] = ctx2[dl] + ctx2[256 + dl];
            if (half == 0) {
                float wv = wsm[tid];
                out[BB * TDEC * ODIM + BB * TDEC + ((size_t)(b * TDEC) + s) * TENC + tid] = wv;
                g_attcum[b * TENC + tid] += wv;
            }
        } else if (bid >= 16 && bid < 57) {
            if (s > 0) {
                int u = (bid - 16) * 16 + w;
                if (u < (ODIM + 1) * BB)
                    outstop_warp(u >> 3, u & 7, s - 1, par, ln, featW, stopW, stopb, out);
            }
        }
        gsync();

        // ============ phase C: LSTM0 (K-split, FFMA2) ============
        if (bid < 128) {
            float* xs = sm;  // [b][1792]
            for (int i = tid; i < 8 * 1792; i += 512) {
                int b = i / 1792, o = i - b * 1792; float v;
                if (o < 512)      v = g_attc[((size_t)(b * TDEC) + s) * DIN + o];
                else if (o < 768) v = g_p2[((size_t)(b * TDEC) + s) * PRE + (o - 512)];
                else              v = g_h0[par][b * DRNN + (o - 768)];
                xs[i] = v;
            }
            __syncthreads();
            int jj = w >> 1, half = w & 1;
            int j = bid * 8 + jj;
            unsigned long long acc2[4][8];
            #pragma unroll
            for (int g = 0; g < 4; g++)
                #pragma unroll
                for (int b = 0; b < 8; b++) acc2[g][b] = 0ull;
            for (int it = 0; it < 7; it++) {
                int qi = half * 224 + it * 32 + ln;   // float4-chunk index in [0,448)
                int xoff = qi * 4;
                ulonglong2 wv[4];
                if (qi < 192) {
                    #pragma unroll
                    for (int g = 0; g < 4; g++)
                        wv[g] = *(const ulonglong2*)(Wi0 + (size_t)(g * 1024 + j) * 768 + xoff);
                } else {
                    int q2 = (qi - 192) * 4;
                    #pragma unroll
                    for (int g = 0; g < 4; g++)
                        wv[g] = *(const ulonglong2*)(Wh0 + (size_t)(g * 1024 + j) * 1024 + q2);
                }
                #pragma unroll
                for (int b = 0; b < 8; b++) {
                    ulonglong2 xv = *(const ulonglong2*)(xs + b * 1792 + xoff);
                    #pragma unroll
                    for (int g = 0; g < 4; g++) {
                        fma2(acc2[g][b], wv[g].x, xv.x);
                        fma2(acc2[g][b], wv[g].y, xv.y);
                    }
                }
            }
            float* P = sm + OFF_PART;
            #pragma unroll
            for (int g = 0; g < 4; g++)
                #pragma unroll
                for (int b = 0; b < 8; b++) {
                    float v = warp_sum(unpack_sum(acc2[g][b]));
                    if (ln == 0) P[((jj * 2 + half) * 4 + g) * 8 + b] = v;
                }
            __syncthreads();
            if (tid < 64) {
                int jj2 = tid >> 3, b = tid & 7, j2 = bid * 8 + jj2;
                float gi = P[((jj2*2)*4+0)*8+b] + P[((jj2*2+1)*4+0)*8+b] + bl0[j2];
                float gf = P[((jj2*2)*4+1)*8+b] + P[((jj2*2+1)*4+1)*8+b] + bl0[j2 + 1024];
                float gg = P[((jj2*2)*4+2)*8+b] + P[((jj2*2+1)*4+2)*8+b] + bl0[j2 + 2048];
                float go = P[((jj2*2)*4+3)*8+b] + P[((jj2*2+1)*4+3)*8+b] + bl0[j2 + 3072];
                int idx = b * DRNN + j2;
                float co = g_c0[par][idx], ho = g_h0[par][idx];
                float cn = sigm(gf) * co + sigm(gi) * tanh_f(gg);
                float hn = sigm(go) * tanh_f(cn);
                g_c0[nxt][idx] = 0.9f * cn + 0.1f * co;
                g_h0[nxt][idx] = 0.9f * hn + 0.1f * ho;
            }
        }
        gsync();

        // ============ phase E: LSTM1 (K-split, FFMA2) + q for next step ============
        if (bid < 128) {
            float* xs = sm;  // [b][2048]
            for (int i = tid; i < 8 * 2048; i += 512) {
                int b = i >> 11, o = i & 2047;
                xs[i] = (o < 1024) ? g_h0[nxt][b * DRNN + o] : g_h1[par][b * DRNN + (o - 1024)];
            }
            __syncthreads();
            int jj = w >> 1, half = w & 1;
            int j = bid * 8 + jj;
            unsigned long long acc2[4][8];
            #pragma unroll
            for (int g = 0; g < 4; g++)
                #pragma unroll
                for (int b = 0; b < 8; b++) acc2[g][b] = 0ull;
            for (int it = 0; it < 8; it++) {
                int qi = half * 256 + it * 32 + ln;   // float4-chunk in [0,512)
                int xoff = qi * 4;
                ulonglong2 wv[4];
                if (qi < 256) {
                    #pragma unroll
                    for (int g = 0; g < 4; g++)
                        wv[g] = *(const ulonglong2*)(Wi1 + (size_t)(g * 1024 + j) * 1024 + xoff);
                } else {
                    int q2 = (qi - 256) * 4;
                    #pragma unroll
                    for (int g = 0; g < 4; g++)
                        wv[g] = *(const ulonglong2*)(Wh1 + (size_t)(g * 1024 + j) * 1024 + q2);
                }
                #pragma unroll
                for (int b = 0; b < 8; b++) {
                    ulonglong2 xv = *(const ulonglong2*)(xs + b * 2048 + xoff);
                    #pragma unroll
                    for (int g = 0; g < 4; g++) {
                        fma2(acc2[g][b], wv[g].x, xv.x);
                        fma2(acc2[g][b], wv[g].y, xv.y);
                    }
                }
            }
            float* P = sm + OFF_PART;
            #pragma unroll
            for (int g = 0; g < 4; g++)
                #pragma unroll
                for (int b = 0; b < 8; b++) {
                    float v = warp_sum(unpack_sum(acc2[g][b]));
                    if (ln == 0) P[((jj * 2 + half) * 4 + g) * 8 + b] = v;
                }
            __syncthreads();
            if (tid < 64) {
                int jj2 = tid >> 3, b = tid & 7, j2 = bid * 8 + jj2;
                float gi = P[((jj2*2)*4+0)*8+b] + P[((jj2*2+1)*4+0)*8+b] + bl1[j2];
                float gf = P[((jj2*2)*4+1)*8+b] + P[((jj2*2+1)*4+1)*8+b] + bl1[j2 + 1024];
                float gg = P[((jj2*2)*4+2)*8+b] + P[((jj2*2+1)*4+2)*8+b] + bl1[j2 + 2048];
                float go = P[((jj2*2)*4+3)*8+b] + P[((jj2*2+1)*4+3)*8+b] + bl1[j2 + 3072];
                int idx = b * DRNN + j2;
                float co = g_c1[par][idx], ho = g_h1[par][idx];
                float cn = sigm(gf) * co + sigm(gi) * tanh_f(gg);
                float hn = sigm(go) * tanh_f(cn);
                g_c1[nxt][idx] = 0.9f * cn + 0.1f * co;
                g_h1[nxt][idx] = 0.9f * hn + 0.1f * ho;
            }
        } else if (bid < 144) {
            // q = h0_new @ Wq^T for next step (16 blocks: (b, a-half))
            int k = bid - 128, qb = k >> 1, ah = (k & 1) * 64;
            float* hs = sm;
            for (int i = tid; i < 1024; i += 512) hs[i] = g_h0[nxt][qb * DRNN + i];
            __syncthreads();
            int a0 = ah + w * 4;
            #pragma unroll
            for (int i = 0; i < 4; i++) {
                const float4* wr = (const float4*)(Wq + (size_t)(a0 + i) * DRNN);
                float acc = 0.f;
                #pragma unroll
                for (int kk = 0; kk < 8; kk++) {
                    float4 wv = wr[ln + kk * 32];
                    float4 hv = *(const float4*)(hs + (ln + kk * 32) * 4);
                    acc += wv.x*hv.x + wv.y*hv.y + wv.z*hv.z + wv.w*hv.w;
                }
                acc = warp_sum(acc);
                if (ln == 0) g_q[qb * ATTN + a0 + i] = acc;
            }
        }
        gsync();
    }

    // ---- final out/stop for step 149 (h1 in buffer 0) ----
    if (bid >= 16 && bid < 57) {
        int u = (bid - 16) * 16 + w;
        if (u < (ODIM + 1) * BB)
            outstop_warp(u >> 3, u & 7, TDEC - 1, 0, ln, featW, stopW, stopb, out);
    }
}

extern "C" void kernel_launch(void* const* d_in, const int* in_sizes, int n_in,
                              void* d_out, int out_size) {
    const float* mem   = (const float*)d_in[0];
    const int*   mlen  = (const int*)  d_in[1];
    const float* tgt   = (const float*)d_in[2];
    const float* Wmem  = (const float*)d_in[3];
    const float* Wq    = (const float*)d_in[4];
    const float* Wloc  = (const float*)d_in[5];
    const float* filt  = (const float*)d_in[6];
    const float* av    = (const float*)d_in[7];
    const float* ab    = (const float*)d_in[8];
    const float* pW1   = (const float*)d_in[9];
    const float* pb1   = (const float*)d_in[10];
    const float* pW2   = (const float*)d_in[11];
    const float* pb2   = (const float*)d_in[12];
    const float* Wi0   = (const float*)d_in[13];
    const float* Wh0   = (const float*)d_in[14];
    const float* bl0   = (const float*)d_in[15];
    const float* Wi1   = (const float*)d_in[16];
    const float* Wh1   = (const float*)d_in[17];
    const float* bl1   = (const float*)d_in[18];
    const float* featW = (const float*)d_in[19];
    const float* stopW = (const float*)d_in[20];
    const float* stopb = (const float*)d_in[21];
    float* out = (float*)d_out;

    static bool attr_set = false;
    if (!attr_set) {
        cudaFuncSetAttribute(decoder_persistent,
                             cudaFuncAttributeMaxDynamicSharedMemorySize,
                             SMEM_FLOATS * 4);
        attr_set = true;
    }

    init_kernel<<<32, 256>>>();
    pm_kernel<<<512, 256>>>(mem, Wmem);
    prenet_kernel<<<BB * TDEC, 256>>>(tgt, pW1, pb1, pW2, pb2);
    decoder_persistent<<<NBLK, 512, SMEM_FLOATS * 4>>>(
        mem, mlen, Wq, Wloc, filt, av, ab,
        Wi0, Wh0, bl0, Wi1, Wh1, bl1, featW, stopW, stopb, out);
}

// round 12
// speedup vs baseline: 1.1686x; 1.1448x over previous
#include <cuda_runtime.h>
#include <cuda_bf16.h>
#include <math.h>

#define BB    8
#define TENC  512
#define DIN   512
#define TDEC  150
#define ODIM  80
#define DRNN  1024
#define PRE   256
#define ATTN  128
#define LOC   32
#define KF    31
#define NBLK  148

// smem float offsets
#define OFF_PART  16384          // 512 floats gate partials, then 64 floats h0 stash
#define OFF_ACON  17024          // A-phase constants: Wl 4096 | flt 992 | vv 128
#define SMEM_FLOATS (OFF_ACON + 5216)

// ---------------- device scratch ----------------
__device__ __align__(16) float g_pm[BB * TENC * ATTN];
__device__ __align__(16) float g_e[BB * TENC];
__device__ __align__(16) float g_attcum[BB * TENC];
__device__ __align__(16) float g_attc[BB * TDEC * DIN];
__device__ __align__(16) float g_p2[BB * TDEC * PRE];
__device__ __align__(16) float g_qp[128 * BB * ATTN];   // per-C-block q partials
__device__ __align__(16) float g_h0[2][BB * DRNN];
__device__ __align__(16) float g_c0[2][BB * DRNN];
__device__ __align__(16) float g_h1[2][BB * DRNN];
__device__ __align__(16) float g_c1[2][BB * DRNN];

__device__ unsigned g_bar_count = 0;
__device__ unsigned g_bar_gen = 0;

// ---------------- helpers ----------------
__device__ __forceinline__ float warp_sum(float v) {
    #pragma unroll
    for (int o = 16; o; o >>= 1) v += __shfl_down_sync(0xffffffffu, v, o);
    return v;
}
__device__ __forceinline__ float sigm(float x) { return 1.0f / (1.0f + __expf(-x)); }
__device__ __forceinline__ float tanh_f(float x) {
    float xc = fminf(fmaxf(x, -10.0f), 10.0f);
    float e = __expf(2.0f * xc);
    return __fdividef(e - 1.0f, e + 1.0f);
}
__device__ __forceinline__ float tanh_hw(float x) {
    float y;
    asm("tanh.approx.f32 %0, %1;" : "=f"(y) : "f"(x));
    return y;
}

// grid-wide barrier (148 blocks, 1/SM)
__device__ __forceinline__ void gsync() {
    __syncthreads();
    if (threadIdx.x == 0) {
        __threadfence();
        unsigned gen = *((volatile unsigned*)&g_bar_gen);
        if (atomicAdd(&g_bar_count, 1u) == NBLK - 1) {
            atomicExch(&g_bar_count, 0u);
            __threadfence();
            atomicExch(&g_bar_gen, gen + 1u);
        } else {
            while (*((volatile unsigned*)&g_bar_gen) == gen) {}
        }
    }
    __syncthreads();
}

// chunked weight loads for the K-split LSTM GEMMs
__device__ __forceinline__ float4 ldw_c(const float* __restrict__ Wi,
                                        const float* __restrict__ Wh,
                                        int g, int j, int qi, int ln) {
    const float* base = (qi < 6)
        ? (Wi + ((size_t)(g * 1024 + j)) * 768 + qi * 128)
        : (Wh + ((size_t)(g * 1024 + j)) * 1024 + (qi - 6) * 128);
    return ((const float4*)base)[ln];
}
__device__ __forceinline__ float4 ldw_e(const float* __restrict__ Wi,
                                        const float* __restrict__ Wh,
                                        int g, int j, int qi, int ln) {
    const float* base = (qi < 8)
        ? (Wi + ((size_t)(g * 1024 + j)) * 1024 + qi * 128)
        : (Wh + ((size_t)(g * 1024 + j)) * 1024 + (qi - 8) * 128);
    return ((const float4*)base)[ln];
}

// ---------------- init ----------------
__global__ void init_kernel() {
    int i = blockIdx.x * 256 + threadIdx.x;
    if (i < BB * DRNN) {
        g_h0[0][i] = 0.f; g_h0[1][i] = 0.f;
        g_c0[0][i] = 0.f; g_c0[1][i] = 0.f;
        g_h1[0][i] = 0.f; g_h1[1][i] = 0.f;
        g_c1[0][i] = 0.f; g_c1[1][i] = 0.f;
    }
    if (i < BB * TENC) g_attcum[i] = 0.f;
    if (i < 128 * BB * ATTN) g_qp[i] = 0.f;
}

// ---------------- processed memory ----------------
__global__ __launch_bounds__(256) void pm_kernel(const float* __restrict__ mem,
                                                 const float* __restrict__ Wmem) {
    int b = blockIdx.x >> 6;
    int t0 = (blockIdx.x & 63) * 8;
    __shared__ __align__(16) float smb[8 * DIN];
    const float* mptr = mem + ((size_t)b * TENC + t0) * DIN;
    for (int i = threadIdx.x; i < 8 * DIN; i += 256) smb[i] = mptr[i];
    __syncthreads();
    int w = threadIdx.x >> 5, ln = threadIdx.x & 31;
    for (int ai = 0; ai < 16; ai++) {
        int a = w * 16 + ai;
        const float4* wr = (const float4*)(Wmem + (size_t)a * DIN);
        float acc[8] = {0,0,0,0,0,0,0,0};
        #pragma unroll
        for (int it = 0; it < 4; it++) {
            float4 wv = wr[ln + it * 32];
            #pragma unroll
            for (int t = 0; t < 8; t++) {
                float4 hv = *(const float4*)(smb + t * DIN + (ln + it * 32) * 4);
                acc[t] += wv.x*hv.x + wv.y*hv.y + wv.z*hv.z + wv.w*hv.w;
            }
        }
        #pragma unroll
        for (int t = 0; t < 8; t++) {
            float v = warp_sum(acc[t]);
            if (ln == 0) g_pm[((size_t)(b * TENC) + (t0 + t)) * ATTN + a] = v;
        }
    }
}

// ---------------- prenet ----------------
__global__ __launch_bounds__(256) void prenet_kernel(const float* __restrict__ tgt,
        const float* __restrict__ W1, const float* __restrict__ b1,
        const float* __restrict__ W2, const float* __restrict__ b2) {
    int b = blockIdx.x / TDEC, s = blockIdx.x % TDEC;
    __shared__ float prev[80];
    __shared__ float p1s[PRE];
    int tid = threadIdx.x;
    if (tid < 80) prev[tid] = (s == 0) ? 0.f : tgt[((size_t)b * TDEC + (s - 1)) * ODIM + tid];
    __syncthreads();
    int w = tid >> 5, ln = tid & 31;
    for (int oi = 0; oi < 32; oi++) {
        int o = w * 32 + oi;
        float acc = 0.f;
        int k = ln * 4;
        if (k < 80) {
            float4 wv = *(const float4*)(W1 + (size_t)o * 80 + k);
            acc = wv.x*prev[k] + wv.y*prev[k+1] + wv.z*prev[k+2] + wv.w*prev[k+3];
        }
        acc = warp_sum(acc);
        if (ln == 0) p1s[o] = fmaxf(acc + b1[o], 0.f);
    }
    __syncthreads();
    for (int oi = 0; oi < 32; oi++) {
        int o = w * 32 + oi;
        float acc = 0.f;
        #pragma unroll
        for (int it = 0; it < 2; it++) {
            int k = ln * 4 + it * 128;
            float4 wv = *(const float4*)(W2 + (size_t)o * PRE + k);
            acc += wv.x*p1s[k] + wv.y*p1s[k+1] + wv.z*p1s[k+2] + wv.w*p1s[k+3];
        }
        acc = warp_sum(acc);
        if (ln == 0) g_p2[((size_t)b * TDEC + s) * PRE + o] = fmaxf(acc + b2[o], 0.f);
    }
}

// ---------------- out/stop projection (warp per (col,b)) ----------------
__device__ __forceinline__ void outstop_warp(int col, int b, int sprev, int h1buf, int ln,
        const float* __restrict__ featW, const float* __restrict__ stopW,
        const float* __restrict__ stopb, float* __restrict__ out) {
    const float4* wr = (const float4*)((col < ODIM) ? (featW + (size_t)col * 1536) : stopW);
    const float4* h1p = (const float4*)(g_h1[h1buf] + b * DRNN);
    const float4* acp = (const float4*)(g_attc + ((size_t)(b * TDEC) + sprev) * DIN);
    float acc = 0.f;
    #pragma unroll
    for (int it = 0; it < 8; it++) {
        float4 wv = wr[ln + it * 32];
        float4 zv = h1p[ln + it * 32];
        acc += wv.x*zv.x + wv.y*zv.y + wv.z*zv.z + wv.w*zv.w;
    }
    #pragma unroll
    for (int it = 0; it < 4; it++) {
        float4 wv = wr[256 + ln + it * 32];
        float4 zv = acp[ln + it * 32];
        acc += wv.x*zv.x + wv.y*zv.y + wv.z*zv.z + wv.w*zv.w;
    }
    acc = warp_sum(acc);
    if (ln == 0) {
        if (col < ODIM) out[((size_t)(b * TDEC) + sprev) * ODIM + col] = acc;
        else            out[BB * TDEC * ODIM + b * TDEC + sprev] = acc + stopb[0];
    }
}

// ---------------- persistent decoder ----------------
__global__ __launch_bounds__(512) void decoder_persistent(
        const float* __restrict__ mem, const int* __restrict__ mlen,
        const float* __restrict__ Wq, const float* __restrict__ Wloc,
        const float* __restrict__ filt, const float* __restrict__ av,
        const float* __restrict__ ab,
        const float* __restrict__ Wi0, const float* __restrict__ Wh0,
        const float* __restrict__ bl0,
        const float* __restrict__ Wi1, const float* __restrict__ Wh1,
        const float* __restrict__ bl1,
        const float* __restrict__ featW, const float* __restrict__ stopW,
        const float* __restrict__ stopb, float* __restrict__ out)
{
    extern __shared__ __align__(16) float sm[];
    const int bid = blockIdx.x, tid = threadIdx.x;
    const int w = tid >> 5, ln = tid & 31;
    const bool isA = (bid >= 132);

    // A-block loop-invariant constants
    if (isA) {
        float* Wl  = sm + OFF_ACON;          // [a*32+c]
        float* flt = sm + OFF_ACON + 4096;   // [c*31+k]
        float* vv  = sm + OFF_ACON + 5088;
        for (int i = tid; i < 4096; i += 512) Wl[i] = Wloc[i];
        for (int i = tid; i < 992; i += 512) flt[i] = filt[i];
        if (tid < 128) vv[tid] = av[tid];
    }
    __syncthreads();

    for (int s = 0; s <= TDEC; s++) {
        const int ep = s & 1;

        // ===== P1: E(s-1) on blocks 0..127  ||  A(s) on blocks 132..147 =====
        if (s > 0 && bid < 128) {
            // LSTM1 for step s-1: x=[h0 after C(s-1) (buf ep) | h1 entering (buf ep^1)]
            float* xs = sm;   // 8*2048
            for (int i = tid; i < 8 * 2048; i += 512) {
                int b = i >> 11, o = i & 2047;
                xs[i] = (o < 1024) ? g_h0[ep][b * DRNN + o] : g_h1[ep ^ 1][b * DRNN + (o - 1024)];
            }
            __syncthreads();
            int jj = w >> 1, half = w & 1;
            int j = bid * 8 + jj;
            int qi0 = half * 8;
            float4 wn[4];
            #pragma unroll
            for (int g = 0; g < 4; g++) wn[g] = ldw_e(Wi1, Wh1, g, j, qi0, ln);
            float acc[4][8];
            #pragma unroll
            for (int g = 0; g < 4; g++)
                #pragma unroll
                for (int b = 0; b < 8; b++) acc[g][b] = 0.f;
            for (int it = 0; it < 8; it++) {
                int qi = qi0 + it;
                float4 wc[4];
                #pragma unroll
                for (int g = 0; g < 4; g++) wc[g] = wn[g];
                if (it < 7) {
                    #pragma unroll
                    for (int g = 0; g < 4; g++) wn[g] = ldw_e(Wi1, Wh1, g, j, qi + 1, ln);
                }
                int xo = qi * 128 + ln * 4;
                #pragma unroll
                for (int b = 0; b < 8; b++) {
                    float4 xv = *(const float4*)(xs + b * 2048 + xo);
                    #pragma unroll
                    for (int g = 0; g < 4; g++)
                        acc[g][b] += wc[g].x*xv.x + wc[g].y*xv.y + wc[g].z*xv.z + wc[g].w*xv.w;
                }
            }
            float* P = sm + OFF_PART;
            #pragma unroll
            for (int g = 0; g < 4; g++)
                #pragma unroll
                for (int b = 0; b < 8; b++) {
                    float v = warp_sum(acc[g][b]);
                    if (ln == 0) P[((jj * 2 + half) * 4 + g) * 8 + b] = v;
                }
            __syncthreads();
            if (tid < 64) {
                int jj2 = tid >> 3, b = tid & 7, j2 = bid * 8 + jj2;
                float gi = P[((jj2*2)*4+0)*8+b] + P[((jj2*2+1)*4+0)*8+b] + bl1[j2];
                float gf = P[((jj2*2)*4+1)*8+b] + P[((jj2*2+1)*4+1)*8+b] + bl1[j2 + 1024];
                float gg = P[((jj2*2)*4+2)*8+b] + P[((jj2*2+1)*4+2)*8+b] + bl1[j2 + 2048];
                float go = P[((jj2*2)*4+3)*8+b] + P[((jj2*2+1)*4+3)*8+b] + bl1[j2 + 3072];
                int idx = b * DRNN + j2;
                float co = g_c1[ep ^ 1][idx], ho = g_h1[ep ^ 1][idx];
                float cn = sigm(gf) * co + sigm(gi) * tanh_f(gg);
                float hn = sigm(go) * tanh_f(cn);
                g_c1[ep][idx] = 0.9f * cn + 0.1f * co;
                g_h1[ep][idx] = 0.9f * hn + 0.1f * ho;
            }
        } else if (s < TDEC && isA) {
            // attention energies for step s; block = (b, t-half)
            const int ablk = bid - 132;
            const int b = ablk >> 1, tbase = (ablk & 1) * 256;
            float* qs   = sm;            // 128
            float* part = sm + 128;      // 512
            float* cumw = sm + 640;      // 272
            float* fsb  = sm + 912;      // 32*33 = 1056
            float* eps  = sm + 1968;     // 512
            const float* Wl  = sm + OFF_ACON;
            const float* flt = sm + OFF_ACON + 4096;
            const float* vv  = sm + OFF_ACON + 5088;
            // reduce q partials (from C(s-1)); zero at s=0 via init
            {
                int a = tid & 127, qtr = tid >> 7;
                float accq = 0.f;
                #pragma unroll 4
                for (int blk = qtr * 32; blk < qtr * 32 + 32; blk++)
                    accq += g_qp[blk * 1024 + b * 128 + a];
                part[qtr * 128 + a] = accq;
            }
            for (int i = tid; i < 271; i += 512) {
                int t = tbase - 15 + i;
                cumw[i] = (t >= 0 && t < TENC) ? g_attcum[b * TENC + t] : 0.f;
            }
            __syncthreads();
            if (tid < 128)
                qs[tid] = part[tid] + part[128 + tid] + part[256 + tid] + part[384 + tid] + ab[tid];
            __syncthreads();
            for (int it = 0; it < 8; it++) {
                int t0 = tbase + it * 32;
                #pragma unroll
                for (int hf = 0; hf < 2; hf++) {
                    int c = w + hf * 16;
                    float f = 0.f;
                    #pragma unroll
                    for (int k = 0; k < KF; k++) f += cumw[it * 32 + ln + k] * flt[c * KF + k];
                    fsb[ln * 33 + c] = f;
                }
                __syncthreads();
                float accA[8];
                #pragma unroll
                for (int i = 0; i < 8; i++) accA[i] = 0.f;
                #pragma unroll 4
                for (int c = 0; c < 32; c++) {
                    float fv = fsb[ln * 33 + c];
                    #pragma unroll
                    for (int i = 0; i < 8; i++)
                        accA[i] += fv * Wl[(w * 8 + i) * 32 + c];
                }
                const float4* pmp = (const float4*)(g_pm + ((size_t)(b * TENC) + t0 + ln) * ATTN + w * 8);
                float ep_ = 0.f;
                #pragma unroll
                for (int v4 = 0; v4 < 2; v4++) {
                    float4 p = pmp[v4];
                    int a = w * 8 + v4 * 4;
                    ep_ += vv[a    ] * tanh_hw(p.x + accA[v4*4    ] + qs[a    ]);
                    ep_ += vv[a + 1] * tanh_hw(p.y + accA[v4*4 + 1] + qs[a + 1]);
                    ep_ += vv[a + 2] * tanh_hw(p.z + accA[v4*4 + 2] + qs[a + 2]);
                    ep_ += vv[a + 3] * tanh_hw(p.w + accA[v4*4 + 3] + qs[a + 3]);
                }
                eps[w * 32 + ln] = ep_;
                __syncthreads();
                if (w == 0) {
                    float e = 0.f;
                    #pragma unroll
                    for (int ww = 0; ww < 16; ww++) e += eps[ww * 32 + ln];
                    g_e[b * TENC + t0 + ln] = e;
                }
                __syncthreads();
            }
        }
        gsync();

        // ===== P2: B(s) on blocks 0..15  ||  outstop(s-1) on blocks 16..56 =====
        if (s < TDEC && bid < 16) {
            const int b = bid >> 1, half = bid & 1;
            float* wsm  = sm;          // 512
            float* red  = sm + 512;    // 16
            float* ctx2 = sm + 528;    // 512
            int len = mlen[b];
            const float* epv = g_e + b * TENC;
            float e0 = (tid < len) ? epv[tid] : -1e9f;
            float mx = e0;
            #pragma unroll
            for (int o = 16; o; o >>= 1) mx = fmaxf(mx, __shfl_xor_sync(0xffffffffu, mx, o));
            if (ln == 0) red[w] = mx;
            __syncthreads();
            mx = red[0];
            #pragma unroll
            for (int ww = 1; ww < 16; ww++) mx = fmaxf(mx, red[ww]);
            float x0 = __expf(e0 - mx);
            float sw = warp_sum(x0);
            __syncthreads();
            if (ln == 0) red[w] = sw;
            __syncthreads();
            float S = 0.f;
            #pragma unroll
            for (int ww = 0; ww < 16; ww++) S += red[ww];
            float inv = __fdividef(1.0f, S);
            wsm[tid] = x0 * inv;
            __syncthreads();
            int tg = tid >> 8, dl = tid & 255;
            int d = half * 256 + dl;
            const float* mp = mem + ((size_t)b * TENC) * DIN + d;
            float a0 = 0.f, a1 = 0.f;
            #pragma unroll 2
            for (int t = tg * 256; t < tg * 256 + 256; t += 2) {
                a0 += wsm[t    ] * mp[(size_t)(t    ) * DIN];
                a1 += wsm[t + 1] * mp[(size_t)(t + 1) * DIN];
            }
            ctx2[tid] = a0 + a1;
            __syncthreads();
            if (tg == 0)
                g_attc[((size_t)(b * TDEC) + s) * DIN + d] = ctx2[dl] + ctx2[256 + dl];
            if (half == 0) {
                float wv = wsm[tid];
                out[BB * TDEC * ODIM + BB * TDEC + ((size_t)(b * TDEC) + s) * TENC + tid] = wv;
                g_attcum[b * TENC + tid] += wv;
            }
        } else if (s > 0 && bid >= 16 && bid < 57) {
            int u = (bid - 16) * 16 + w;
            if (u < (ODIM + 1) * BB)
                outstop_warp(u >> 3, u & 7, s - 1, ep, ln, featW, stopW, stopb, out);
        }
        if (s == TDEC) break;
        gsync();

        // ===== P3: C(s) + q partials, blocks 0..127 =====
        if (bid < 128) {
            float* xs = sm;  // 8*1792
            for (int i = tid; i < 8 * 1792; i += 512) {
                int b = i / 1792, o = i - b * 1792; float v;
                if (o < 512)      v = g_attc[((size_t)(b * TDEC) + s) * DIN + o];
                else if (o < 768) v = g_p2[((size_t)(b * TDEC) + s) * PRE + (o - 512)];
                else              v = g_h0[ep][b * DRNN + (o - 768)];
                xs[i] = v;
            }
            __syncthreads();
            int jj = w >> 1, half = w & 1;
            int j = bid * 8 + jj;
            int qi0 = half * 7;
            float4 wn[4];
            #pragma unroll
            for (int g = 0; g < 4; g++) wn[g] = ldw_c(Wi0, Wh0, g, j, qi0, ln);
            float acc[4][8];
            #pragma unroll
            for (int g = 0; g < 4; g++)
                #pragma unroll
                for (int b = 0; b < 8; b++) acc[g][b] = 0.f;
            for (int it = 0; it < 7; it++) {
                int qi = qi0 + it;
                float4 wc[4];
                #pragma unroll
                for (int g = 0; g < 4; g++) wc[g] = wn[g];
                if (it < 6) {
                    #pragma unroll
                    for (int g = 0; g < 4; g++) wn[g] = ldw_c(Wi0, Wh0, g, j, qi + 1, ln);
                }
                int xo = qi * 128 + ln * 4;
                #pragma unroll
                for (int b = 0; b < 8; b++) {
                    float4 xv = *(const float4*)(xs + b * 1792 + xo);
                    #pragma unroll
                    for (int g = 0; g < 4; g++)
                        acc[g][b] += wc[g].x*xv.x + wc[g].y*xv.y + wc[g].z*xv.z + wc[g].w*xv.w;
                }
            }
            float* P = sm + OFF_PART;
            float* h0s = sm + OFF_PART + 512;
            #pragma unroll
            for (int g = 0; g < 4; g++)
                #pragma unroll
                for (int b = 0; b < 8; b++) {
                    float v = warp_sum(acc[g][b]);
                    if (ln == 0) P[((jj * 2 + half) * 4 + g) * 8 + b] = v;
                }
            __syncthreads();
            if (tid < 64) {
                int jj2 = tid >> 3, b = tid & 7, j2 = bid * 8 + jj2;
                float gi = P[((jj2*2)*4+0)*8+b] + P[((jj2*2+1)*4+0)*8+b] + bl0[j2];
                float gf = P[((jj2*2)*4+1)*8+b] + P[((jj2*2+1)*4+1)*8+b] + bl0[j2 + 1024];
                float gg = P[((jj2*2)*4+2)*8+b] + P[((jj2*2+1)*4+2)*8+b] + bl0[j2 + 2048];
                float go = P[((jj2*2)*4+3)*8+b] + P[((jj2*2+1)*4+3)*8+b] + bl0[j2 + 3072];
                int idx = b * DRNN + j2;
                float co = g_c0[ep][idx], ho = g_h0[ep][idx];
                float cn = sigm(gf) * co + sigm(gi) * tanh_f(gg);
                float hn = sigm(go) * tanh_f(cn);
                float hmix = 0.9f * hn + 0.1f * ho;
                g_c0[ep ^ 1][idx] = 0.9f * cn + 0.1f * co;
                g_h0[ep ^ 1][idx] = hmix;
                h0s[jj2 * 8 + b] = hmix;
            }
            __syncthreads();
            // deterministic q partials for step s+1: this block's 8 j's
            if (tid < 128) {
                int a = tid;
                float4 wq1 = *(const float4*)(Wq + (size_t)a * DRNN + bid * 8);
                float4 wq2 = *(const float4*)(Wq + (size_t)a * DRNN + bid * 8 + 4);
                #pragma unroll
                for (int b = 0; b < 8; b++) {
                    float sq = wq1.x*h0s[0*8+b] + wq1.y*h0s[1*8+b] + wq1.z*h0s[2*8+b] + wq1.w*h0s[3*8+b]
                             + wq2.x*h0s[4*8+b] + wq2.y*h0s[5*8+b] + wq2.z*h0s[6*8+b] + wq2.w*h0s[7*8+b];
                    g_qp[bid * 1024 + b * 128 + a] = sq;
                }
            }
        }
        gsync();
    }
}

extern "C" void kernel_launch(void* const* d_in, const int* in_sizes, int n_in,
                              void* d_out, int out_size) {
    const float* mem   = (const float*)d_in[0];
    const int*   mlen  = (const int*)  d_in[1];
    const float* tgt   = (const float*)d_in[2];
    const float* Wmem  = (const float*)d_in[3];
    const float* Wq    = (const float*)d_in[4];
    const float* Wloc  = (const float*)d_in[5];
    const float* filt  = (const float*)d_in[6];
    const float* av    = (const float*)d_in[7];
    const float* ab    = (const float*)d_in[8];
    const float* pW1   = (const float*)d_in[9];
    const float* pb1   = (const float*)d_in[10];
    const float* pW2   = (const float*)d_in[11];
    const float* pb2   = (const float*)d_in[12];
    const float* Wi0   = (const float*)d_in[13];
    const float* Wh0   = (const float*)d_in[14];
    const float* bl0   = (const float*)d_in[15];
    const float* Wi1   = (const float*)d_in[16];
    const float* Wh1   = (const float*)d_in[17];
    const float* bl1   = (const float*)d_in[18];
    const float* featW = (const float*)d_in[19];
    const float* stopW = (const float*)d_in[20];
    const float* stopb = (const float*)d_in[21];
    float* out = (float*)d_out;

    static bool attr_set = false;
    if (!attr_set) {
        cudaFuncSetAttribute(decoder_persistent,
                             cudaFuncAttributeMaxDynamicSharedMemorySize,
                             SMEM_FLOATS * 4);
        attr_set = true;
    }

    init_kernel<<<512, 256>>>();
    pm_kernel<<<512, 256>>>(mem, Wmem);
    prenet_kernel<<<BB * TDEC, 256>>>(tgt, pW1, pb1, pW2, pb2);
    decoder_persistent<<<NBLK, 512, SMEM_FLOATS * 4>>>(
        mem, mlen, Wq, Wloc, filt, av, ab,
        Wi0, Wh0, bl0, Wi1, Wh1, bl1, featW, stopW, stopb, out);
}

// round 13
// speedup vs baseline: 1.4882x; 1.2734x over previous
#include <cuda_runtime.h>
#include <cuda_bf16.h>
#include <math.h>

#define BB    8
#define TENC  512
#define DIN   512
#define TDEC  150
#define ODIM  80
#define DRNN  1024
#define PRE   256
#define ATTN  128
#define LOC   32
#define KF    31
#define NBLK  148

// smem float offsets
#define OFF_PART  16384          // 512 floats gate partials + 64 floats h0 stash
#define OFF_ACON  17024          // constants: Wl 4096 | flt 992 | vv 128
#define SMEM_FLOATS (OFF_ACON + 5216)

// ---------------- device scratch ----------------
__device__ __align__(16) float g_pm[BB * TENC * ATTN];
__device__ __align__(16) float g_e[BB * TENC];
__device__ __align__(16) float g_attcum[BB * TENC];
__device__ __align__(16) float g_attc[BB * TDEC * DIN];
__device__ __align__(16) float g_p2[BB * TDEC * PRE];
__device__ __align__(16) float g_qp[128 * BB * ATTN];   // per-C-block q partials
__device__ __align__(16) float g_h0[2][BB * DRNN];
__device__ __align__(16) float g_c0[2][BB * DRNN];
__device__ __align__(16) float g_h1[2][BB * DRNN];
__device__ __align__(16) float g_c1[2][BB * DRNN];

__device__ unsigned g_bar_count = 0;
__device__ unsigned g_bar_gen = 0;

// ---------------- helpers ----------------
__device__ __forceinline__ float warp_sum(float v) {
    #pragma unroll
    for (int o = 16; o; o >>= 1) v += __shfl_down_sync(0xffffffffu, v, o);
    return v;
}
__device__ __forceinline__ float sigm(float x) { return 1.0f / (1.0f + __expf(-x)); }
__device__ __forceinline__ float tanh_f(float x) {
    float xc = fminf(fmaxf(x, -10.0f), 10.0f);
    float e = __expf(2.0f * xc);
    return __fdividef(e - 1.0f, e + 1.0f);
}
__device__ __forceinline__ float tanh_hw(float x) {
    float y;
    asm("tanh.approx.f32 %0, %1;" : "=f"(y) : "f"(x));
    return y;
}

// grid-wide barrier (148 blocks, 1/SM)
__device__ __forceinline__ void gsync() {
    __syncthreads();
    if (threadIdx.x == 0) {
        __threadfence();
        unsigned gen = *((volatile unsigned*)&g_bar_gen);
        if (atomicAdd(&g_bar_count, 1u) == NBLK - 1) {
            atomicExch(&g_bar_count, 0u);
            __threadfence();
            atomicExch(&g_bar_gen, gen + 1u);
        } else {
            while (*((volatile unsigned*)&g_bar_gen) == gen) {}
        }
    }
    __syncthreads();
}

// chunked weight loads for the K-split LSTM GEMMs
__device__ __forceinline__ float4 ldw_c(const float* __restrict__ Wi,
                                        const float* __restrict__ Wh,
                                        int g, int j, int qi, int ln) {
    const float* base = (qi < 6)
        ? (Wi + ((size_t)(g * 1024 + j)) * 768 + qi * 128)
        : (Wh + ((size_t)(g * 1024 + j)) * 1024 + (qi - 6) * 128);
    return ((const float4*)base)[ln];
}
__device__ __forceinline__ float4 ldw_e(const float* __restrict__ Wi,
                                        const float* __restrict__ Wh,
                                        int g, int j, int qi, int ln) {
    const float* base = (qi < 8)
        ? (Wi + ((size_t)(g * 1024 + j)) * 1024 + qi * 128)
        : (Wh + ((size_t)(g * 1024 + j)) * 1024 + (qi - 8) * 128);
    return ((const float4*)base)[ln];
}

// ---------------- init ----------------
__global__ void init_kernel() {
    int i = blockIdx.x * 256 + threadIdx.x;
    if (i < BB * DRNN) {
        g_h0[0][i] = 0.f; g_h0[1][i] = 0.f;
        g_c0[0][i] = 0.f; g_c0[1][i] = 0.f;
        g_h1[0][i] = 0.f; g_h1[1][i] = 0.f;
        g_c1[0][i] = 0.f; g_c1[1][i] = 0.f;
    }
    if (i < BB * TENC) g_attcum[i] = 0.f;
    if (i < 128 * BB * ATTN) g_qp[i] = 0.f;
}

// ---------------- processed memory ----------------
__global__ __launch_bounds__(256) void pm_kernel(const float* __restrict__ mem,
                                                 const float* __restrict__ Wmem) {
    int b = blockIdx.x >> 6;
    int t0 = (blockIdx.x & 63) * 8;
    __shared__ __align__(16) float smb[8 * DIN];
    const float* mptr = mem + ((size_t)b * TENC + t0) * DIN;
    for (int i = threadIdx.x; i < 8 * DIN; i += 256) smb[i] = mptr[i];
    __syncthreads();
    int w = threadIdx.x >> 5, ln = threadIdx.x & 31;
    for (int ai = 0; ai < 16; ai++) {
        int a = w * 16 + ai;
        const float4* wr = (const float4*)(Wmem + (size_t)a * DIN);
        float acc[8] = {0,0,0,0,0,0,0,0};
        #pragma unroll
        for (int it = 0; it < 4; it++) {
            float4 wv = wr[ln + it * 32];
            #pragma unroll
            for (int t = 0; t < 8; t++) {
                float4 hv = *(const float4*)(smb + t * DIN + (ln + it * 32) * 4);
                acc[t] += wv.x*hv.x + wv.y*hv.y + wv.z*hv.z + wv.w*hv.w;
            }
        }
        #pragma unroll
        for (int t = 0; t < 8; t++) {
            float v = warp_sum(acc[t]);
            if (ln == 0) g_pm[((size_t)(b * TENC) + (t0 + t)) * ATTN + a] = v;
        }
    }
}

// ---------------- prenet ----------------
__global__ __launch_bounds__(256) void prenet_kernel(const float* __restrict__ tgt,
        const float* __restrict__ W1, const float* __restrict__ b1,
        const float* __restrict__ W2, const float* __restrict__ b2) {
    int b = blockIdx.x / TDEC, s = blockIdx.x % TDEC;
    __shared__ float prev[80];
    __shared__ float p1s[PRE];
    int tid = threadIdx.x;
    if (tid < 80) prev[tid] = (s == 0) ? 0.f : tgt[((size_t)b * TDEC + (s - 1)) * ODIM + tid];
    __syncthreads();
    int w = tid >> 5, ln = tid & 31;
    for (int oi = 0; oi < 32; oi++) {
        int o = w * 32 + oi;
        float acc = 0.f;
        int k = ln * 4;
        if (k < 80) {
            float4 wv = *(const float4*)(W1 + (size_t)o * 80 + k);
            acc = wv.x*prev[k] + wv.y*prev[k+1] + wv.z*prev[k+2] + wv.w*prev[k+3];
        }
        acc = warp_sum(acc);
        if (ln == 0) p1s[o] = fmaxf(acc + b1[o], 0.f);
    }
    __syncthreads();
    for (int oi = 0; oi < 32; oi++) {
        int o = w * 32 + oi;
        float acc = 0.f;
        #pragma unroll
        for (int it = 0; it < 2; it++) {
            int k = ln * 4 + it * 128;
            float4 wv = *(const float4*)(W2 + (size_t)o * PRE + k);
            acc += wv.x*p1s[k] + wv.y*p1s[k+1] + wv.z*p1s[k+2] + wv.w*p1s[k+3];
        }
        acc = warp_sum(acc);
        if (ln == 0) g_p2[((size_t)b * TDEC + s) * PRE + o] = fmaxf(acc + b2[o], 0.f);
    }
}

// ---------------- out/stop projection (warp per (col,b)) ----------------
__device__ __forceinline__ void outstop_warp(int col, int b, int sprev, int h1buf, int ln,
        const float* __restrict__ featW, const float* __restrict__ stopW,
        const float* __restrict__ stopb, float* __restrict__ out) {
    const float4* wr = (const float4*)((col < ODIM) ? (featW + (size_t)col * 1536) : stopW);
    const float4* h1p = (const float4*)(g_h1[h1buf] + b * DRNN);
    const float4* acp = (const float4*)(g_attc + ((size_t)(b * TDEC) + sprev) * DIN);
    float acc = 0.f;
    #pragma unroll
    for (int it = 0; it < 8; it++) {
        float4 wv = wr[ln + it * 32];
        float4 zv = h1p[ln + it * 32];
        acc += wv.x*zv.x + wv.y*zv.y + wv.z*zv.z + wv.w*zv.w;
    }
    #pragma unroll
    for (int it = 0; it < 4; it++) {
        float4 wv = wr[256 + ln + it * 32];
        float4 zv = acp[ln + it * 32];
        acc += wv.x*zv.x + wv.y*zv.y + wv.z*zv.z + wv.w*zv.w;
    }
    acc = warp_sum(acc);
    if (ln == 0) {
        if (col < ODIM) out[((size_t)(b * TDEC) + sprev) * ODIM + col] = acc;
        else            out[BB * TDEC * ODIM + b * TDEC + sprev] = acc + stopb[0];
    }
}

// ---------------- persistent decoder ----------------
__global__ __launch_bounds__(512) void decoder_persistent(
        const float* __restrict__ mem, const int* __restrict__ mlen,
        const float* __restrict__ Wq, const float* __restrict__ Wloc,
        const float* __restrict__ filt, const float* __restrict__ av,
        const float* __restrict__ ab,
        const float* __restrict__ Wi0, const float* __restrict__ Wh0,
        const float* __restrict__ bl0,
        const float* __restrict__ Wi1, const float* __restrict__ Wh1,
        const float* __restrict__ bl1,
        const float* __restrict__ featW, const float* __restrict__ stopW,
        const float* __restrict__ stopb, float* __restrict__ out)
{
    extern __shared__ __align__(16) float sm[];
    const int bid = blockIdx.x, tid = threadIdx.x;
    const int w = tid >> 5, ln = tid & 31;

    // loop-invariant attention constants (blocks 0..127 run the A phase)
    if (bid < 128) {
        float* Wl  = sm + OFF_ACON;          // [a*32+c]
        float* flt = sm + OFF_ACON + 4096;   // [c*31+k]
        float* vv  = sm + OFF_ACON + 5088;
        for (int i = tid; i < 4096; i += 512) Wl[i] = Wloc[i];
        for (int i = tid; i < 992; i += 512) flt[i] = filt[i];
        if (tid < 128) vv[tid] = av[tid];
    }
    __syncthreads();

    for (int s = 0; s <= TDEC; s++) {
        const int ep = s & 1;

        // ===== P1: blocks 0..127 do E(s-1), then A(s) =====
        if (bid < 128) {
            if (s > 0) {
                // LSTM1 for step s-1
                float* xs = sm;   // 8*2048
                for (int i = tid; i < 8 * 2048; i += 512) {
                    int b = i >> 11, o = i & 2047;
                    xs[i] = (o < 1024) ? g_h0[ep][b * DRNN + o] : g_h1[ep ^ 1][b * DRNN + (o - 1024)];
                }
                __syncthreads();
                int jj = w >> 1, half = w & 1;
                int j = bid * 8 + jj;
                int qi0 = half * 8;
                float4 wn[4];
                #pragma unroll
                for (int g = 0; g < 4; g++) wn[g] = ldw_e(Wi1, Wh1, g, j, qi0, ln);
                float acc[4][8];
                #pragma unroll
                for (int g = 0; g < 4; g++)
                    #pragma unroll
                    for (int b = 0; b < 8; b++) acc[g][b] = 0.f;
                for (int it = 0; it < 8; it++) {
                    int qi = qi0 + it;
                    float4 wc[4];
                    #pragma unroll
                    for (int g = 0; g < 4; g++) wc[g] = wn[g];
                    if (it < 7) {
                        #pragma unroll
                        for (int g = 0; g < 4; g++) wn[g] = ldw_e(Wi1, Wh1, g, j, qi + 1, ln);
                    }
                    int xo = qi * 128 + ln * 4;
                    #pragma unroll
                    for (int b = 0; b < 8; b++) {
                        float4 xv = *(const float4*)(xs + b * 2048 + xo);
                        #pragma unroll
                        for (int g = 0; g < 4; g++)
                            acc[g][b] += wc[g].x*xv.x + wc[g].y*xv.y + wc[g].z*xv.z + wc[g].w*xv.w;
                    }
                }
                float* P = sm + OFF_PART;
                #pragma unroll
                for (int g = 0; g < 4; g++)
                    #pragma unroll
                    for (int b = 0; b < 8; b++) {
                        float v = warp_sum(acc[g][b]);
                        if (ln == 0) P[((jj * 2 + half) * 4 + g) * 8 + b] = v;
                    }
                __syncthreads();
                if (tid < 64) {
                    int jj2 = tid >> 3, b = tid & 7, j2 = bid * 8 + jj2;
                    float gi = P[((jj2*2)*4+0)*8+b] + P[((jj2*2+1)*4+0)*8+b] + bl1[j2];
                    float gf = P[((jj2*2)*4+1)*8+b] + P[((jj2*2+1)*4+1)*8+b] + bl1[j2 + 1024];
                    float gg = P[((jj2*2)*4+2)*8+b] + P[((jj2*2+1)*4+2)*8+b] + bl1[j2 + 2048];
                    float go = P[((jj2*2)*4+3)*8+b] + P[((jj2*2+1)*4+3)*8+b] + bl1[j2 + 3072];
                    int idx = b * DRNN + j2;
                    float co = g_c1[ep ^ 1][idx], ho = g_h1[ep ^ 1][idx];
                    float cn = sigm(gf) * co + sigm(gi) * tanh_f(gg);
                    float hn = sigm(go) * tanh_f(cn);
                    g_c1[ep][idx] = 0.9f * cn + 0.1f * co;
                    g_h1[ep][idx] = 0.9f * hn + 0.1f * ho;
                }
            }
            if (s < TDEC) {
                // ---- A(s): attention energies, 128 blocks = (b, 32-t tile) ----
                __syncthreads();
                const int b = bid >> 4, t0 = (bid & 15) * 32;
                float* qs   = sm;            // 128
                float* part = sm + 128;      // 512
                float* fs   = sm + 640;      // 32*33 = 1056
                float* cum  = sm + 1696;     // 64
                float* eps  = sm + 1760;     // 512
                const float* Wl  = sm + OFF_ACON;
                const float* flt = sm + OFF_ACON + 4096;
                const float* vv  = sm + OFF_ACON + 5088;
                {
                    int a = tid & 127, qtr = tid >> 7;
                    float accq = 0.f;
                    #pragma unroll 4
                    for (int blk = qtr * 32; blk < qtr * 32 + 32; blk++)
                        accq += g_qp[blk * 1024 + b * 128 + a];
                    part[qtr * 128 + a] = accq;
                }
                if (tid < 64) {
                    int t = t0 - 15 + tid;
                    cum[tid] = (t >= 0 && t < TENC) ? g_attcum[b * TENC + t] : 0.f;
                }
                __syncthreads();
                if (tid < 128)
                    qs[tid] = part[tid] + part[128 + tid] + part[256 + tid] + part[384 + tid] + ab[tid];
                __syncthreads();
                #pragma unroll
                for (int hf = 0; hf < 2; hf++) {
                    int c = w + hf * 16;
                    float f = 0.f;
                    #pragma unroll
                    for (int k = 0; k < KF; k++) f += cum[ln + k] * flt[c * KF + k];
                    fs[ln * 33 + c] = f;
                }
                __syncthreads();
                float accA[8];
                #pragma unroll
                for (int i = 0; i < 8; i++) accA[i] = 0.f;
                #pragma unroll 4
                for (int c = 0; c < 32; c++) {
                    float fv = fs[ln * 33 + c];
                    #pragma unroll
                    for (int i = 0; i < 8; i++)
                        accA[i] += fv * Wl[(w * 8 + i) * 32 + c];
                }
                const float4* pmp = (const float4*)(g_pm + ((size_t)(b * TENC) + t0 + ln) * ATTN + w * 8);
                float ep_ = 0.f;
                #pragma unroll
                for (int v4 = 0; v4 < 2; v4++) {
                    float4 p = pmp[v4];
                    int a = w * 8 + v4 * 4;
                    ep_ += vv[a    ] * tanh_hw(p.x + accA[v4*4    ] + qs[a    ]);
                    ep_ += vv[a + 1] * tanh_hw(p.y + accA[v4*4 + 1] + qs[a + 1]);
                    ep_ += vv[a + 2] * tanh_hw(p.z + accA[v4*4 + 2] + qs[a + 2]);
                    ep_ += vv[a + 3] * tanh_hw(p.w + accA[v4*4 + 3] + qs[a + 3]);
                }
                eps[w * 32 + ln] = ep_;
                __syncthreads();
                if (w == 0) {
                    float e = 0.f;
                    #pragma unroll
                    for (int ww = 0; ww < 16; ww++) e += eps[ww * 32 + ln];
                    g_e[b * TENC + t0 + ln] = e;
                }
            }
        }
        gsync();

        // ===== P2: B(s) on blocks 0..15  ||  outstop(s-1) on blocks 16..56 =====
        if (s < TDEC && bid < 16) {
            const int b = bid >> 1, half = bid & 1;
            float* wsm  = sm;          // 512
            float* red  = sm + 512;    // 16
            float* ctx2 = sm + 528;    // 512
            int len = mlen[b];
            const float* epv = g_e + b * TENC;
            float e0 = (tid < len) ? epv[tid] : -1e9f;
            float mx = e0;
            #pragma unroll
            for (int o = 16; o; o >>= 1) mx = fmaxf(mx, __shfl_xor_sync(0xffffffffu, mx, o));
            if (ln == 0) red[w] = mx;
            __syncthreads();
            mx = red[0];
            #pragma unroll
            for (int ww = 1; ww < 16; ww++) mx = fmaxf(mx, red[ww]);
            float x0 = __expf(e0 - mx);
            float sw = warp_sum(x0);
            __syncthreads();
            if (ln == 0) red[w] = sw;
            __syncthreads();
            float S = 0.f;
            #pragma unroll
            for (int ww = 0; ww < 16; ww++) S += red[ww];
            float inv = __fdividef(1.0f, S);
            wsm[tid] = x0 * inv;
            __syncthreads();
            int tg = tid >> 8, dl = tid & 255;
            int d = half * 256 + dl;
            const float* mp = mem + ((size_t)b * TENC) * DIN + d;
            float a0 = 0.f, a1 = 0.f;
            #pragma unroll 2
            for (int t = tg * 256; t < tg * 256 + 256; t += 2) {
                a0 += wsm[t    ] * mp[(size_t)(t    ) * DIN];
                a1 += wsm[t + 1] * mp[(size_t)(t + 1) * DIN];
            }
            ctx2[tid] = a0 + a1;
            __syncthreads();
            if (tg == 0)
                g_attc[((size_t)(b * TDEC) + s) * DIN + d] = ctx2[dl] + ctx2[256 + dl];
            if (half == 0) {
                float wv = wsm[tid];
                out[BB * TDEC * ODIM + BB * TDEC + ((size_t)(b * TDEC) + s) * TENC + tid] = wv;
                g_attcum[b * TENC + tid] += wv;
            }
        } else if (s > 0 && bid >= 16 && bid < 57) {
            int u = (bid - 16) * 16 + w;
            if (u < (ODIM + 1) * BB)
                outstop_warp(u >> 3, u & 7, s - 1, ep, ln, featW, stopW, stopb, out);
        }
        if (s == TDEC) break;
        gsync();

        // ===== P3: C(s) + q partials, blocks 0..127 =====
        if (bid < 128) {
            float* xs = sm;  // 8*1792
            for (int i = tid; i < 8 * 1792; i += 512) {
                int b = i / 1792, o = i - b * 1792; float v;
                if (o < 512)      v = g_attc[((size_t)(b * TDEC) + s) * DIN + o];
                else if (o < 768) v = g_p2[((size_t)(b * TDEC) + s) * PRE + (o - 512)];
                else              v = g_h0[ep][b * DRNN + (o - 768)];
                xs[i] = v;
            }
            __syncthreads();
            int jj = w >> 1, half = w & 1;
            int j = bid * 8 + jj;
            int qi0 = half * 7;
            float4 wn[4];
            #pragma unroll
            for (int g = 0; g < 4; g++) wn[g] = ldw_c(Wi0, Wh0, g, j, qi0, ln);
            float acc[4][8];
            #pragma unroll
            for (int g = 0; g < 4; g++)
                #pragma unroll
                for (int b = 0; b < 8; b++) acc[g][b] = 0.f;
            for (int it = 0; it < 7; it++) {
                int qi = qi0 + it;
                float4 wc[4];
                #pragma unroll
                for (int g = 0; g < 4; g++) wc[g] = wn[g];
                if (it < 6) {
                    #pragma unroll
                    for (int g = 0; g < 4; g++) wn[g] = ldw_c(Wi0, Wh0, g, j, qi + 1, ln);
                }
                int xo = qi * 128 + ln * 4;
                #pragma unroll
                for (int b = 0; b < 8; b++) {
                    float4 xv = *(const float4*)(xs + b * 1792 + xo);
                    #pragma unroll
                    for (int g = 0; g < 4; g++)
                        acc[g][b] += wc[g].x*xv.x + wc[g].y*xv.y + wc[g].z*xv.z + wc[g].w*xv.w;
                }
            }
            float* P = sm + OFF_PART;
            float* h0s = sm + OFF_PART + 512;
            #pragma unroll
            for (int g = 0; g < 4; g++)
                #pragma unroll
                for (int b = 0; b < 8; b++) {
                    float v = warp_sum(acc[g][b]);
                    if (ln == 0) P[((jj * 2 + half) * 4 + g) * 8 + b] = v;
                }
            __syncthreads();
            if (tid < 64) {
                int jj2 = tid >> 3, b = tid & 7, j2 = bid * 8 + jj2;
                float gi = P[((jj2*2)*4+0)*8+b] + P[((jj2*2+1)*4+0)*8+b] + bl0[j2];
                float gf = P[((jj2*2)*4+1)*8+b] + P[((jj2*2+1)*4+1)*8+b] + bl0[j2 + 1024];
                float gg = P[((jj2*2)*4+2)*8+b] + P[((jj2*2+1)*4+2)*8+b] + bl0[j2 + 2048];
                float go = P[((jj2*2)*4+3)*8+b] + P[((jj2*2+1)*4+3)*8+b] + bl0[j2 + 3072];
                int idx = b * DRNN + j2;
                float co = g_c0[ep][idx], ho = g_h0[ep][idx];
                float cn = sigm(gf) * co + sigm(gi) * tanh_f(gg);
                float hn = sigm(go) * tanh_f(cn);
                float hmix = 0.9f * hn + 0.1f * ho;
                g_c0[ep ^ 1][idx] = 0.9f * cn + 0.1f * co;
                g_h0[ep ^ 1][idx] = hmix;
                h0s[jj2 * 8 + b] = hmix;
            }
            __syncthreads();
            // deterministic q partials for step s+1
            if (tid < 128) {
                int a = tid;
                float4 wq1 = *(const float4*)(Wq + (size_t)a * DRNN + bid * 8);
                float4 wq2 = *(const float4*)(Wq + (size_t)a * DRNN + bid * 8 + 4);
                #pragma unroll
                for (int b = 0; b < 8; b++) {
                    float sq = wq1.x*h0s[0*8+b] + wq1.y*h0s[1*8+b] + wq1.z*h0s[2*8+b] + wq1.w*h0s[3*8+b]
                             + wq2.x*h0s[4*8+b] + wq2.y*h0s[5*8+b] + wq2.z*h0s[6*8+b] + wq2.w*h0s[7*8+b];
                    g_qp[bid * 1024 + b * 128 + a] = sq;
                }
            }
        }
        gsync();
    }
}

extern "C" void kernel_launch(void* const* d_in, const int* in_sizes, int n_in,
                              void* d_out, int out_size) {
    const float* mem   = (const float*)d_in[0];
    const int*   mlen  = (const int*)  d_in[1];
    const float* tgt   = (const float*)d_in[2];
    const float* Wmem  = (const float*)d_in[3];
    const float* Wq    = (const float*)d_in[4];
    const float* Wloc  = (const float*)d_in[5];
    const float* filt  = (const float*)d_in[6];
    const float* av    = (const float*)d_in[7];
    const float* ab    = (const float*)d_in[8];
    const float* pW1   = (const float*)d_in[9];
    const float* pb1   = (const float*)d_in[10];
    const float* pW2   = (const float*)d_in[11];
    const float* pb2   = (const float*)d_in[12];
    const float* Wi0   = (const float*)d_in[13];
    const float* Wh0   = (const float*)d_in[14];
    const float* bl0   = (const float*)d_in[15];
    const float* Wi1   = (const float*)d_in[16];
    const float* Wh1   = (const float*)d_in[17];
    const float* bl1   = (const float*)d_in[18];
    const float* featW = (const float*)d_in[19];
    const float* stopW = (const float*)d_in[20];
    const float* stopb = (const float*)d_in[21];
    float* out = (float*)d_out;

    static bool attr_set = false;
    if (!attr_set) {
        cudaFuncSetAttribute(decoder_persistent,
                             cudaFuncAttributeMaxDynamicSharedMemorySize,
                             SMEM_FLOATS * 4);
        attr_set = true;
    }

    init_kernel<<<512, 256>>>();
    pm_kernel<<<512, 256>>>(mem, Wmem);
    prenet_kernel<<<BB * TDEC, 256>>>(tgt, pW1, pb1, pW2, pb2);
    decoder_persistent<<<NBLK, 512, SMEM_FLOATS * 4>>>(
        mem, mlen, Wq, Wloc, filt, av, ab,
        Wi0, Wh0, bl0, Wi1, Wh1, bl1, featW, stopW, stopb, out);
}

// round 14
// speedup vs baseline: 2.1834x; 1.4672x over previous
#include <cuda_runtime.h>
#include <cuda_bf16.h>
#include <math.h>

#define BB    8
#define TENC  512
#define DIN   512
#define TDEC  150
#define ODIM  80
#define DRNN  1024
#define PRE   256
#define ATTN  128
#define LOC   32
#define KF    31
#define NBLK  148

// smem float offsets
#define OFF_PART  16384          // 512 floats gate partials + 64 floats h0 stash
#define OFF_ACON  17024          // constants: Wl 4096 | flt 992 | vv 128
#define SMEM_FLOATS (OFF_ACON + 5216)

// ---------------- device scratch ----------------
__device__ __align__(16) float g_pm[BB * TENC * ATTN];
__device__ __align__(16) float g_e[BB * TENC];
__device__ __align__(16) float g_attcum[BB * TENC];
__device__ __align__(16) float g_attc[BB * TDEC * DIN];
__device__ __align__(16) float g_p2[BB * TDEC * PRE];
__device__ __align__(16) float g_qp[128 * BB * ATTN];   // per-C-block q partials
__device__ __align__(16) float g_h0[2][BB * DRNN];
__device__ __align__(16) float g_c0[2][BB * DRNN];
__device__ __align__(16) float g_h1[2][BB * DRNN];
__device__ __align__(16) float g_c1[2][BB * DRNN];

__device__ unsigned g_bar_count = 0;
__device__ unsigned g_bar_gen = 0;

// ---------------- helpers ----------------
__device__ __forceinline__ float warp_sum(float v) {
    #pragma unroll
    for (int o = 16; o; o >>= 1) v += __shfl_down_sync(0xffffffffu, v, o);
    return v;
}
__device__ __forceinline__ float sigm(float x) { return 1.0f / (1.0f + __expf(-x)); }
__device__ __forceinline__ float tanh_f(float x) {
    float xc = fminf(fmaxf(x, -10.0f), 10.0f);
    float e = __expf(2.0f * xc);
    return __fdividef(e - 1.0f, e + 1.0f);
}
__device__ __forceinline__ float tanh_hw(float x) {
    float y;
    asm("tanh.approx.f32 %0, %1;" : "=f"(y) : "f"(x));
    return y;
}

// grid-wide barrier (148 blocks, 1/SM)
__device__ __forceinline__ void gsync() {
    __syncthreads();
    if (threadIdx.x == 0) {
        __threadfence();
        unsigned gen = *((volatile unsigned*)&g_bar_gen);
        if (atomicAdd(&g_bar_count, 1u) == NBLK - 1) {
            atomicExch(&g_bar_count, 0u);
            __threadfence();
            atomicExch(&g_bar_gen, gen + 1u);
        } else {
            while (*((volatile unsigned*)&g_bar_gen) == gen) {}
        }
    }
    __syncthreads();
}

// ---------------- init ----------------
__global__ void init_kernel() {
    int i = blockIdx.x * 256 + threadIdx.x;
    if (i < BB * DRNN) {
        g_h0[0][i] = 0.f; g_h0[1][i] = 0.f;
        g_c0[0][i] = 0.f; g_c0[1][i] = 0.f;
        g_h1[0][i] = 0.f; g_h1[1][i] = 0.f;
        g_c1[0][i] = 0.f; g_c1[1][i] = 0.f;
    }
    if (i < BB * TENC) g_attcum[i] = 0.f;
    if (i < 128 * BB * ATTN) g_qp[i] = 0.f;
}

// ---------------- processed memory ----------------
__global__ __launch_bounds__(256) void pm_kernel(const float* __restrict__ mem,
                                                 const float* __restrict__ Wmem) {
    int b = blockIdx.x >> 6;
    int t0 = (blockIdx.x & 63) * 8;
    __shared__ __align__(16) float smb[8 * DIN];
    const float* mptr = mem + ((size_t)b * TENC + t0) * DIN;
    for (int i = threadIdx.x; i < 8 * DIN; i += 256) smb[i] = mptr[i];
    __syncthreads();
    int w = threadIdx.x >> 5, ln = threadIdx.x & 31;
    for (int ai = 0; ai < 16; ai++) {
        int a = w * 16 + ai;
        const float4* wr = (const float4*)(Wmem + (size_t)a * DIN);
        float acc[8] = {0,0,0,0,0,0,0,0};
        #pragma unroll
        for (int it = 0; it < 4; it++) {
            float4 wv = wr[ln + it * 32];
            #pragma unroll
            for (int t = 0; t < 8; t++) {
                float4 hv = *(const float4*)(smb + t * DIN + (ln + it * 32) * 4);
                acc[t] += wv.x*hv.x + wv.y*hv.y + wv.z*hv.z + wv.w*hv.w;
            }
        }
        #pragma unroll
        for (int t = 0; t < 8; t++) {
            float v = warp_sum(acc[t]);
            if (ln == 0) g_pm[((size_t)(b * TENC) + (t0 + t)) * ATTN + a] = v;
        }
    }
}

// ---------------- prenet ----------------
__global__ __launch_bounds__(256) void prenet_kernel(const float* __restrict__ tgt,
        const float* __restrict__ W1, const float* __restrict__ b1,
        const float* __restrict__ W2, const float* __restrict__ b2) {
    int b = blockIdx.x / TDEC, s = blockIdx.x % TDEC;
    __shared__ float prev[80];
    __shared__ float p1s[PRE];
    int tid = threadIdx.x;
    if (tid < 80) prev[tid] = (s == 0) ? 0.f : tgt[((size_t)b * TDEC + (s - 1)) * ODIM + tid];
    __syncthreads();
    int w = tid >> 5, ln = tid & 31;
    for (int oi = 0; oi < 32; oi++) {
        int o = w * 32 + oi;
        float acc = 0.f;
        int k = ln * 4;
        if (k < 80) {
            float4 wv = *(const float4*)(W1 + (size_t)o * 80 + k);
            acc = wv.x*prev[k] + wv.y*prev[k+1] + wv.z*prev[k+2] + wv.w*prev[k+3];
        }
        acc = warp_sum(acc);
        if (ln == 0) p1s[o] = fmaxf(acc + b1[o], 0.f);
    }
    __syncthreads();
    for (int oi = 0; oi < 32; oi++) {
        int o = w * 32 + oi;
        float acc = 0.f;
        #pragma unroll
        for (int it = 0; it < 2; it++) {
            int k = ln * 4 + it * 128;
            float4 wv = *(const float4*)(W2 + (size_t)o * PRE + k);
            acc += wv.x*p1s[k] + wv.y*p1s[k+1] + wv.z*p1s[k+2] + wv.w*p1s[k+3];
        }
        acc = warp_sum(acc);
        if (ln == 0) g_p2[((size_t)b * TDEC + s) * PRE + o] = fmaxf(acc + b2[o], 0.f);
    }
}

// ---------------- out/stop projection (warp per (col,b)) ----------------
__device__ __forceinline__ void outstop_warp(int col, int b, int sprev, int h1buf, int ln,
        const float* __restrict__ featW, const float* __restrict__ stopW,
        const float* __restrict__ stopb, float* __restrict__ out) {
    const float4* wr = (const float4*)((col < ODIM) ? (featW + (size_t)col * 1536) : stopW);
    const float4* h1p = (const float4*)(g_h1[h1buf] + b * DRNN);
    const float4* acp = (const float4*)(g_attc + ((size_t)(b * TDEC) + sprev) * DIN);
    float acc = 0.f;
    #pragma unroll
    for (int it = 0; it < 8; it++) {
        float4 wv = wr[ln + it * 32];
        float4 zv = h1p[ln + it * 32];
        acc += wv.x*zv.x + wv.y*zv.y + wv.z*zv.z + wv.w*zv.w;
    }
    #pragma unroll
    for (int it = 0; it < 4; it++) {
        float4 wv = wr[256 + ln + it * 32];
        float4 zv = acp[ln + it * 32];
        acc += wv.x*zv.x + wv.y*zv.y + wv.z*zv.z + wv.w*zv.w;
    }
    acc = warp_sum(acc);
    if (ln == 0) {
        if (col < ODIM) out[((size_t)(b * TDEC) + sprev) * ODIM + col] = acc;
        else            out[BB * TDEC * ODIM + b * TDEC + sprev] = acc + stopb[0];
    }
}

// ---------------- persistent decoder ----------------
__global__ __launch_bounds__(512) void decoder_persistent(
        const float* __restrict__ mem, const int* __restrict__ mlen,
        const float* __restrict__ Wq, const float* __restrict__ Wloc,
        const float* __restrict__ filt, const float* __restrict__ av,
        const float* __restrict__ ab,
        const float* __restrict__ Wi0, const float* __restrict__ Wh0,
        const float* __restrict__ bl0,
        const float* __restrict__ Wi1, const float* __restrict__ Wh1,
        const float* __restrict__ bl1,
        const float* __restrict__ featW, const float* __restrict__ stopW,
        const float* __restrict__ stopb, float* __restrict__ out)
{
    extern __shared__ __align__(16) float sm[];
    const int bid = blockIdx.x, tid = threadIdx.x;
    const int w = tid >> 5, ln = tid & 31;

    // loop-invariant attention constants (blocks 0..127 run the A phase)
    if (bid < 128) {
        float* Wl  = sm + OFF_ACON;          // [a*32+c]
        float* flt = sm + OFF_ACON + 4096;   // [c*31+k]
        float* vv  = sm + OFF_ACON + 5088;
        for (int i = tid; i < 4096; i += 512) Wl[i] = Wloc[i];
        for (int i = tid; i < 992; i += 512) flt[i] = filt[i];
        if (tid < 128) vv[tid] = av[tid];
    }
    __syncthreads();

    for (int s = 0; s <= TDEC; s++) {
        const int ep = s & 1;

        // ===== P1: blocks 0..127 do E(s-1), then A(s) =====
        if (bid < 128) {
            if (s > 0) {
                // LSTM1 for step s-1
                float* xs = sm;   // 8*2048 floats
                float4* xs4 = (float4*)xs;
                const float4* h0_4 = (const float4*)(g_h0[ep]);
                const float4* h1_4 = (const float4*)(g_h1[ep ^ 1]);
                for (int i = tid; i < 4096; i += 512) {
                    int b = i >> 9, o = i & 511;
                    xs4[i] = (o < 256) ? h0_4[b * 256 + o] : h1_4[b * 256 + (o - 256)];
                }
                __syncthreads();
                int jj = w >> 1, half = w & 1;
                int j = bid * 8 + jj;
                const float4* wr0 = (const float4*)((half ? Wh1 : Wi1) + (size_t)(0 * 1024 + j) * 1024);
                const float4* wr1 = (const float4*)((half ? Wh1 : Wi1) + (size_t)(1 * 1024 + j) * 1024);
                const float4* wr2 = (const float4*)((half ? Wh1 : Wi1) + (size_t)(2 * 1024 + j) * 1024);
                const float4* wr3 = (const float4*)((half ? Wh1 : Wi1) + (size_t)(3 * 1024 + j) * 1024);
                int xbase = half * 1024 + ln * 4;
                float acc[4][8];
                #pragma unroll
                for (int g = 0; g < 4; g++)
                    #pragma unroll
                    for (int b = 0; b < 8; b++) acc[g][b] = 0.f;
                #pragma unroll 2
                for (int it = 0; it < 8; it++) {
                    float4 wv0 = wr0[it * 32 + ln];
                    float4 wv1 = wr1[it * 32 + ln];
                    float4 wv2 = wr2[it * 32 + ln];
                    float4 wv3 = wr3[it * 32 + ln];
                    int xo = xbase + it * 128;
                    #pragma unroll
                    for (int b = 0; b < 8; b++) {
                        float4 xv = *(const float4*)(xs + b * 2048 + xo);
                        acc[0][b] += wv0.x*xv.x + wv0.y*xv.y + wv0.z*xv.z + wv0.w*xv.w;
                        acc[1][b] += wv1.x*xv.x + wv1.y*xv.y + wv1.z*xv.z + wv1.w*xv.w;
                        acc[2][b] += wv2.x*xv.x + wv2.y*xv.y + wv2.z*xv.z + wv2.w*xv.w;
                        acc[3][b] += wv3.x*xv.x + wv3.y*xv.y + wv3.z*xv.z + wv3.w*xv.w;
                    }
                }
                float* P = sm + OFF_PART;
                #pragma unroll
                for (int g = 0; g < 4; g++)
                    #pragma unroll
                    for (int b = 0; b < 8; b++) {
                        float v = warp_sum(acc[g][b]);
                        if (ln == 0) P[((jj * 2 + half) * 4 + g) * 8 + b] = v;
                    }
                __syncthreads();
                if (tid < 64) {
                    int jj2 = tid >> 3, b = tid & 7, j2 = bid * 8 + jj2;
                    float gi = P[((jj2*2)*4+0)*8+b] + P[((jj2*2+1)*4+0)*8+b] + bl1[j2];
                    float gf = P[((jj2*2)*4+1)*8+b] + P[((jj2*2+1)*4+1)*8+b] + bl1[j2 + 1024];
                    float gg = P[((jj2*2)*4+2)*8+b] + P[((jj2*2+1)*4+2)*8+b] + bl1[j2 + 2048];
                    float go = P[((jj2*2)*4+3)*8+b] + P[((jj2*2+1)*4+3)*8+b] + bl1[j2 + 3072];
                    int idx = b * DRNN + j2;
                    float co = g_c1[ep ^ 1][idx], ho = g_h1[ep ^ 1][idx];
                    float cn = sigm(gf) * co + sigm(gi) * tanh_f(gg);
                    float hn = sigm(go) * tanh_f(cn);
                    g_c1[ep][idx] = 0.9f * cn + 0.1f * co;
                    g_h1[ep][idx] = 0.9f * hn + 0.1f * ho;
                }
            }
            if (s < TDEC) {
                // ---- A(s): attention energies, 128 blocks = (b, 32-t tile) ----
                __syncthreads();
                const int b = bid >> 4, t0 = (bid & 15) * 32;
                float* qs   = sm;            // 128
                float* part = sm + 128;      // 512
                float* fs   = sm + 640;      // 32*33 = 1056
                float* cum  = sm + 1696;     // 64
                float* eps  = sm + 1760;     // 512
                const float* Wl  = sm + OFF_ACON;
                const float* flt = sm + OFF_ACON + 4096;
                const float* vv  = sm + OFF_ACON + 5088;
                {
                    int a = tid & 127, qtr = tid >> 7;
                    float accq = 0.f;
                    #pragma unroll 4
                    for (int blk = qtr * 32; blk < qtr * 32 + 32; blk++)
                        accq += g_qp[blk * 1024 + b * 128 + a];
                    part[qtr * 128 + a] = accq;
                }
                if (tid < 64) {
                    int t = t0 - 15 + tid;
                    cum[tid] = (t >= 0 && t < TENC) ? g_attcum[b * TENC + t] : 0.f;
                }
                __syncthreads();
                if (tid < 128)
                    qs[tid] = part[tid] + part[128 + tid] + part[256 + tid] + part[384 + tid] + ab[tid];
                __syncthreads();
                #pragma unroll
                for (int hf = 0; hf < 2; hf++) {
                    int c = w + hf * 16;
                    float f = 0.f;
                    #pragma unroll
                    for (int k = 0; k < KF; k++) f += cum[ln + k] * flt[c * KF + k];
                    fs[ln * 33 + c] = f;
                }
                __syncthreads();
                float accA[8];
                #pragma unroll
                for (int i = 0; i < 8; i++) accA[i] = 0.f;
                #pragma unroll 4
                for (int c = 0; c < 32; c++) {
                    float fv = fs[ln * 33 + c];
                    #pragma unroll
                    for (int i = 0; i < 8; i++)
                        accA[i] += fv * Wl[(w * 8 + i) * 32 + c];
                }
                const float4* pmp = (const float4*)(g_pm + ((size_t)(b * TENC) + t0 + ln) * ATTN + w * 8);
                float ep_ = 0.f;
                #pragma unroll
                for (int v4 = 0; v4 < 2; v4++) {
                    float4 p = pmp[v4];
                    int a = w * 8 + v4 * 4;
                    ep_ += vv[a    ] * tanh_hw(p.x + accA[v4*4    ] + qs[a    ]);
                    ep_ += vv[a + 1] * tanh_hw(p.y + accA[v4*4 + 1] + qs[a + 1]);
                    ep_ += vv[a + 2] * tanh_hw(p.z + accA[v4*4 + 2] + qs[a + 2]);
                    ep_ += vv[a + 3] * tanh_hw(p.w + accA[v4*4 + 3] + qs[a + 3]);
                }
                eps[w * 32 + ln] = ep_;
                __syncthreads();
                if (w == 0) {
                    float e = 0.f;
                    #pragma unroll
                    for (int ww = 0; ww < 16; ww++) e += eps[ww * 32 + ln];
                    g_e[b * TENC + t0 + ln] = e;
                }
            }
        }
        gsync();

        // ===== P2: B(s) on blocks 0..15 only =====
        if (s < TDEC && bid < 16) {
            const int b = bid >> 1, half = bid & 1;
            float* wsm  = sm;                     // 512
            float* red  = sm + 512;               // 16
            float4* ctx4 = (float4*)(sm + 528);   // 8 tg * 64 float4
            int len = mlen[b];
            const float* epv = g_e + b * TENC;
            float e0 = (tid < len) ? epv[tid] : -1e9f;
            float mx = e0;
            #pragma unroll
            for (int o = 16; o; o >>= 1) mx = fmaxf(mx, __shfl_xor_sync(0xffffffffu, mx, o));
            if (ln == 0) red[w] = mx;
            __syncthreads();
            mx = red[0];
            #pragma unroll
            for (int ww = 1; ww < 16; ww++) mx = fmaxf(mx, red[ww]);
            float x0 = __expf(e0 - mx);
            float sw = warp_sum(x0);
            __syncthreads();
            if (ln == 0) red[w] = sw;
            __syncthreads();
            float S = 0.f;
            #pragma unroll
            for (int ww = 0; ww < 16; ww++) S += red[ww];
            float inv = __fdividef(1.0f, S);
            wsm[tid] = x0 * inv;
            __syncthreads();
            // context: 8 t-groups x 64 d-vec4
            int tg = tid >> 6, dl = tid & 63;
            const float4* mp4 = (const float4*)(mem + ((size_t)b * TENC) * DIN + half * 256) + dl;
            float4 a = {0.f, 0.f, 0.f, 0.f};
            #pragma unroll 4
            for (int t = tg * 64; t < tg * 64 + 64; t++) {
                float wv = wsm[t];
                float4 m = mp4[(size_t)t * 128];
                a.x += wv * m.x; a.y += wv * m.y; a.z += wv * m.z; a.w += wv * m.w;
            }
            ctx4[tg * 64 + dl] = a;
            __syncthreads();
            if (tid < 64) {
                float4 sa = ctx4[tid];
                #pragma unroll
                for (int tg2 = 1; tg2 < 8; tg2++) {
                    float4 v = ctx4[tg2 * 64 + tid];
                    sa.x += v.x; sa.y += v.y; sa.z += v.z; sa.w += v.w;
                }
                *(float4*)(g_attc + ((size_t)(b * TDEC) + s) * DIN + half * 256 + tid * 4) = sa;
            }
            if (half == 0) {
                float wv = wsm[tid];
                out[BB * TDEC * ODIM + BB * TDEC + ((size_t)(b * TDEC) + s) * TENC + tid] = wv;
                g_attcum[b * TENC + tid] += wv;
            }
        }
        gsync();

        // ===== P3: C(s)+qp on blocks 0..127  ||  outstop(s-1) on 128..147 =====
        if (s < TDEC && bid < 128) {
            float* xs = sm;  // 8*1792 floats = 8*448 float4
            float4* xs4 = (float4*)xs;
            const float4* h0_4 = (const float4*)(g_h0[ep]);
            for (int i = tid; i < 3584; i += 512) {
                int b = i / 448, o = i - b * 448;
                float4 v;
                if (o < 128)      v = ((const float4*)(g_attc + ((size_t)(b * TDEC) + s) * DIN))[o];
                else if (o < 192) v = ((const float4*)(g_p2 + ((size_t)(b * TDEC) + s) * PRE))[o - 128];
                else              v = h0_4[b * 256 + (o - 192)];
                xs4[i] = v;
            }
            __syncthreads();
            int jj = w >> 1, half = w & 1;
            int j = bid * 8 + jj;
            float acc[4][8];
            #pragma unroll
            for (int g = 0; g < 4; g++)
                #pragma unroll
                for (int b = 0; b < 8; b++) acc[g][b] = 0.f;
            if (half == 0) {
                // Wi0 chunks 0..5 (K=768: attc+p2) + Wh0 chunk 0
                const float4* wr0 = (const float4*)(Wi0 + (size_t)(0 * 1024 + j) * 768);
                const float4* wr1 = (const float4*)(Wi0 + (size_t)(1 * 1024 + j) * 768);
                const float4* wr2 = (const float4*)(Wi0 + (size_t)(2 * 1024 + j) * 768);
                const float4* wr3 = (const float4*)(Wi0 + (size_t)(3 * 1024 + j) * 768);
                #pragma unroll 2
                for (int it = 0; it < 6; it++) {
                    float4 wv0 = wr0[it * 32 + ln];
                    float4 wv1 = wr1[it * 32 + ln];
                    float4 wv2 = wr2[it * 32 + ln];
                    float4 wv3 = wr3[it * 32 + ln];
                    int xo = it * 128 + ln * 4;
                    #pragma unroll
                    for (int b = 0; b < 8; b++) {
                        float4 xv = *(const float4*)(xs + b * 1792 + xo);
                        acc[0][b] += wv0.x*xv.x + wv0.y*xv.y + wv0.z*xv.z + wv0.w*xv.w;
                        acc[1][b] += wv1.x*xv.x + wv1.y*xv.y + wv1.z*xv.z + wv1.w*xv.w;
                        acc[2][b] += wv2.x*xv.x + wv2.y*xv.y + wv2.z*xv.z + wv2.w*xv.w;
                        acc[3][b] += wv3.x*xv.x + wv3.y*xv.y + wv3.z*xv.z + wv3.w*xv.w;
                    }
                }
                {
                    float4 wv0 = ((const float4*)(Wh0 + (size_t)(0 * 1024 + j) * 1024))[ln];
                    float4 wv1 = ((const float4*)(Wh0 + (size_t)(1 * 1024 + j) * 1024))[ln];
                    float4 wv2 = ((const float4*)(Wh0 + (size_t)(2 * 1024 + j) * 1024))[ln];
                    float4 wv3 = ((const float4*)(Wh0 + (size_t)(3 * 1024 + j) * 1024))[ln];
                    int xo = 768 + ln * 4;
                    #pragma unroll
                    for (int b = 0; b < 8; b++) {
                        float4 xv = *(const float4*)(xs + b * 1792 + xo);
                        acc[0][b] += wv0.x*xv.x + wv0.y*xv.y + wv0.z*xv.z + wv0.w*xv.w;
                        acc[1][b] += wv1.x*xv.x + wv1.y*xv.y + wv1.z*xv.z + wv1.w*xv.w;
                        acc[2][b] += wv2.x*xv.x + wv2.y*xv.y + wv2.z*xv.z + wv2.w*xv.w;
                        acc[3][b] += wv3.x*xv.x + wv3.y*xv.y + wv3.z*xv.z + wv3.w*xv.w;
                    }
                }
            } else {
                // Wh0 chunks 1..7
                const float4* wr0 = (const float4*)(Wh0 + (size_t)(0 * 1024 + j) * 1024) + 32;
                const float4* wr1 = (const float4*)(Wh0 + (size_t)(1 * 1024 + j) * 1024) + 32;
                const float4* wr2 = (const float4*)(Wh0 + (size_t)(2 * 1024 + j) * 1024) + 32;
                const float4* wr3 = (const float4*)(Wh0 + (size_t)(3 * 1024 + j) * 1024) + 32;
                #pragma unroll 2
                for (int it = 0; it < 7; it++) {
                    float4 wv0 = wr0[it * 32 + ln];
                    float4 wv1 = wr1[it * 32 + ln];
                    float4 wv2 = wr2[it * 32 + ln];
                    float4 wv3 = wr3[it * 32 + ln];
                    int xo = 768 + (it + 1) * 128 + ln * 4;
                    #pragma unroll
                    for (int b = 0; b < 8; b++) {
                        float4 xv = *(const float4*)(xs + b * 1792 + xo);
                        acc[0][b] += wv0.x*xv.x + wv0.y*xv.y + wv0.z*xv.z + wv0.w*xv.w;
                        acc[1][b] += wv1.x*xv.x + wv1.y*xv.y + wv1.z*xv.z + wv1.w*xv.w;
                        acc[2][b] += wv2.x*xv.x + wv2.y*xv.y + wv2.z*xv.z + wv2.w*xv.w;
                        acc[3][b] += wv3.x*xv.x + wv3.y*xv.y + wv3.z*xv.z + wv3.w*xv.w;
                    }
                }
            }
            float* P = sm + OFF_PART;
            float* h0s = sm + OFF_PART + 512;
            #pragma unroll
            for (int g = 0; g < 4; g++)
                #pragma unroll
                for (int b = 0; b < 8; b++) {
                    float v = warp_sum(acc[g][b]);
                    if (ln == 0) P[((jj * 2 + half) * 4 + g) * 8 + b] = v;
                }
            __syncthreads();
            if (tid < 64) {
                int jj2 = tid >> 3, b = tid & 7, j2 = bid * 8 + jj2;
                float gi = P[((jj2*2)*4+0)*8+b] + P[((jj2*2+1)*4+0)*8+b] + bl0[j2];
                float gf = P[((jj2*2)*4+1)*8+b] + P[((jj2*2+1)*4+1)*8+b] + bl0[j2 + 1024];
                float gg = P[((jj2*2)*4+2)*8+b] + P[((jj2*2+1)*4+2)*8+b] + bl0[j2 + 2048];
                float go = P[((jj2*2)*4+3)*8+b] + P[((jj2*2+1)*4+3)*8+b] + bl0[j2 + 3072];
                int idx = b * DRNN + j2;
                float co = g_c0[ep][idx], ho = g_h0[ep][idx];
                float cn = sigm(gf) * co + sigm(gi) * tanh_f(gg);
                float hn = sigm(go) * tanh_f(cn);
                float hmix = 0.9f * hn + 0.1f * ho;
                g_c0[ep ^ 1][idx] = 0.9f * cn + 0.1f * co;
                g_h0[ep ^ 1][idx] = hmix;
                h0s[jj2 * 8 + b] = hmix;
            }
            __syncthreads();
            // deterministic q partials for step s+1
            if (tid < 128) {
                int a = tid;
                float4 wq1 = *(const float4*)(Wq + (size_t)a * DRNN + bid * 8);
                float4 wq2 = *(const float4*)(Wq + (size_t)a * DRNN + bid * 8 + 4);
                #pragma unroll
                for (int b = 0; b < 8; b++) {
                    float sq = wq1.x*h0s[0*8+b] + wq1.y*h0s[1*8+b] + wq1.z*h0s[2*8+b] + wq1.w*h0s[3*8+b]
                             + wq2.x*h0s[4*8+b] + wq2.y*h0s[5*8+b] + wq2.z*h0s[6*8+b] + wq2.w*h0s[7*8+b];
                    g_qp[bid * 1024 + b * 128 + a] = sq;
                }
            }
        } else if (s > 0 && bid >= 128) {
            // out/stop for step s-1 on 20 side blocks (320 warps, 648 units)
            #pragma unroll
            for (int r = 0; r < 3; r++) {
                int u = (bid - 128) * 16 + w + r * 320;
                if (u < (ODIM + 1) * BB)
                    outstop_warp(u >> 3, u & 7, s - 1, ep, ln, featW, stopW, stopb, out);
            }
        }
        if (s == TDEC) break;
        gsync();
    }
}

extern "C" void kernel_launch(void* const* d_in, const int* in_sizes, int n_in,
                              void* d_out, int out_size) {
    const float* mem   = (const float*)d_in[0];
    const int*   mlen  = (const int*)  d_in[1];
    const float* tgt   = (const float*)d_in[2];
    const float* Wmem  = (const float*)d_in[3];
    const float* Wq    = (const float*)d_in[4];
    const float* Wloc  = (const float*)d_in[5];
    const float* filt  = (const float*)d_in[6];
    const float* av    = (const float*)d_in[7];
    const float* ab    = (const float*)d_in[8];
    const float* pW1   = (const float*)d_in[9];
    const float* pb1   = (const float*)d_in[10];
    const float* pW2   = (const float*)d_in[11];
    const float* pb2   = (const float*)d_in[12];
    const float* Wi0   = (const float*)d_in[13];
    const float* Wh0   = (const float*)d_in[14];
    const float* bl0   = (const float*)d_in[15];
    const float* Wi1   = (const float*)d_in[16];
    const float* Wh1   = (const float*)d_in[17];
    const float* bl1   = (const float*)d_in[18];
    const float* featW = (const float*)d_in[19];
    const float* stopW = (const float*)d_in[20];
    const float* stopb = (const float*)d_in[21];
    float* out = (float*)d_out;

    static bool attr_set = false;
    if (!attr_set) {
        cudaFuncSetAttribute(decoder_persistent,
                             cudaFuncAttributeMaxDynamicSharedMemorySize,
                             SMEM_FLOATS * 4);
        attr_set = true;
    }

    init_kernel<<<512, 256>>>();
    pm_kernel<<<512, 256>>>(mem, Wmem);
    prenet_kernel<<<BB * TDEC, 256>>>(tgt, pW1, pb1, pW2, pb2);
    decoder_persistent<<<NBLK, 512, SMEM_FLOATS * 4>>>(
        mem, mlen, Wq, Wloc, filt, av, ab,
        Wi0, Wh0, bl0, Wi1, Wh1, bl1, featW, stopW, stopb, out);
}

// round 15
// speedup vs baseline: 2.2621x; 1.0360x over previous
#include <cuda_runtime.h>
#include <cuda_bf16.h>
#include <math.h>

#define BB    8
#define TENC  512
#define DIN   512
#define TDEC  150
#define ODIM  80
#define DRNN  1024
#define PRE   256
#define ATTN  128
#define LOC   32
#define KF    31
#define NBLK  148

// smem float offsets (E's transposed xs is the largest user: 2048 rows * 10)
#define OFF_PART  20480          // 512 gate partials + 64 h0 stash
#define OFF_CH    21056          // 512 C_h partials (persist P2 -> P3)
#define OFF_ACON  21568          // constants: Wl 4096 | flt 992 | vv 128
#define SMEM_FLOATS (OFF_ACON + 5216)

// ---------------- device scratch ----------------
__device__ __align__(16) float g_pm[BB * TENC * ATTN];
__device__ __align__(16) float g_e[BB * TENC];
__device__ __align__(16) float g_attcum[BB * TENC];
__device__ __align__(16) float g_attc[BB * TDEC * DIN];
__device__ __align__(16) float g_p2[BB * TDEC * PRE];
__device__ __align__(16) float g_qp[128 * BB * ATTN];   // per-C-block q partials
__device__ __align__(16) float g_h0[2][BB * DRNN];
__device__ __align__(16) float g_c0[2][BB * DRNN];
__device__ __align__(16) float g_h1[2][BB * DRNN];
__device__ __align__(16) float g_c1[2][BB * DRNN];

__device__ unsigned g_bar_count = 0;
__device__ unsigned g_bar_gen = 0;

// ---------------- helpers ----------------
__device__ __forceinline__ float warp_sum(float v) {
    #pragma unroll
    for (int o = 16; o; o >>= 1) v += __shfl_down_sync(0xffffffffu, v, o);
    return v;
}
__device__ __forceinline__ float sigm(float x) { return 1.0f / (1.0f + __expf(-x)); }
__device__ __forceinline__ float tanh_f(float x) {
    float xc = fminf(fmaxf(x, -10.0f), 10.0f);
    float e = __expf(2.0f * xc);
    return __fdividef(e - 1.0f, e + 1.0f);
}
__device__ __forceinline__ float tanh_hw(float x) {
    float y;
    asm("tanh.approx.f32 %0, %1;" : "=f"(y) : "f"(x));
    return y;
}
// packed dual-fp32 FMA: d = a*b + d (elementwise on the two 32-bit lanes)
__device__ __forceinline__ void fma2(unsigned long long& d, unsigned long long a,
                                     unsigned long long b) {
    asm("fma.rn.f32x2 %0, %1, %2, %0;" : "+l"(d) : "l"(a), "l"(b));
}
__device__ __forceinline__ unsigned long long pack_dup(float x) {
    unsigned long long r;
    unsigned int u = __float_as_uint(x);
    asm("mov.b64 %0, {%1, %2};" : "=l"(r) : "r"(u), "r"(u));
    return r;
}

// grid-wide barrier (148 blocks, 1/SM)
__device__ __forceinline__ void gsync() {
    __syncthreads();
    if (threadIdx.x == 0) {
        __threadfence();
        unsigned gen = *((volatile unsigned*)&g_bar_gen);
        if (atomicAdd(&g_bar_count, 1u) == NBLK - 1) {
            atomicExch(&g_bar_count, 0u);
            __threadfence();
            atomicExch(&g_bar_gen, gen + 1u);
        } else {
            while (*((volatile unsigned*)&g_bar_gen) == gen) {}
        }
    }
    __syncthreads();
}

// ---------------- init ----------------
__global__ void init_kernel() {
    int i = blockIdx.x * 256 + threadIdx.x;
    if (i < BB * DRNN) {
        g_h0[0][i] = 0.f; g_h0[1][i] = 0.f;
        g_c0[0][i] = 0.f; g_c0[1][i] = 0.f;
        g_h1[0][i] = 0.f; g_h1[1][i] = 0.f;
        g_c1[0][i] = 0.f; g_c1[1][i] = 0.f;
    }
    if (i < BB * TENC) g_attcum[i] = 0.f;
    if (i < 128 * BB * ATTN) g_qp[i] = 0.f;
}

// ---------------- processed memory ----------------
__global__ __launch_bounds__(256) void pm_kernel(const float* __restrict__ mem,
                                                 const float* __restrict__ Wmem) {
    int b = blockIdx.x >> 6;
    int t0 = (blockIdx.x & 63) * 8;
    __shared__ __align__(16) float smb[8 * DIN];
    const float* mptr = mem + ((size_t)b * TENC + t0) * DIN;
    for (int i = threadIdx.x; i < 8 * DIN; i += 256) smb[i] = mptr[i];
    __syncthreads();
    int w = threadIdx.x >> 5, ln = threadIdx.x & 31;
    for (int ai = 0; ai < 16; ai++) {
        int a = w * 16 + ai;
        const float4* wr = (const float4*)(Wmem + (size_t)a * DIN);
        float acc[8] = {0,0,0,0,0,0,0,0};
        #pragma unroll
        for (int it = 0; it < 4; it++) {
            float4 wv = wr[ln + it * 32];
            #pragma unroll
            for (int t = 0; t < 8; t++) {
                float4 hv = *(const float4*)(smb + t * DIN + (ln + it * 32) * 4);
                acc[t] += wv.x*hv.x + wv.y*hv.y + wv.z*hv.z + wv.w*hv.w;
            }
        }
        #pragma unroll
        for (int t = 0; t < 8; t++) {
            float v = warp_sum(acc[t]);
            if (ln == 0) g_pm[((size_t)(b * TENC) + (t0 + t)) * ATTN + a] = v;
        }
    }
}

// ---------------- prenet ----------------
__global__ __launch_bounds__(256) void prenet_kernel(const float* __restrict__ tgt,
        const float* __restrict__ W1, const float* __restrict__ b1,
        const float* __restrict__ W2, const float* __restrict__ b2) {
    int b = blockIdx.x / TDEC, s = blockIdx.x % TDEC;
    __shared__ float prev[80];
    __shared__ float p1s[PRE];
    int tid = threadIdx.x;
    if (tid < 80) prev[tid] = (s == 0) ? 0.f : tgt[((size_t)b * TDEC + (s - 1)) * ODIM + tid];
    __syncthreads();
    int w = tid >> 5, ln = tid & 31;
    for (int oi = 0; oi < 32; oi++) {
        int o = w * 32 + oi;
        float acc = 0.f;
        int k = ln * 4;
        if (k < 80) {
            float4 wv = *(const float4*)(W1 + (size_t)o * 80 + k);
            acc = wv.x*prev[k] + wv.y*prev[k+1] + wv.z*prev[k+2] + wv.w*prev[k+3];
        }
        acc = warp_sum(acc);
        if (ln == 0) p1s[o] = fmaxf(acc + b1[o], 0.f);
    }
    __syncthreads();
    for (int oi = 0; oi < 32; oi++) {
        int o = w * 32 + oi;
        float acc = 0.f;
        #pragma unroll
        for (int it = 0; it < 2; it++) {
            int k = ln * 4 + it * 128;
            float4 wv = *(const float4*)(W2 + (size_t)o * PRE + k);
            acc += wv.x*p1s[k] + wv.y*p1s[k+1] + wv.z*p1s[k+2] + wv.w*p1s[k+3];
        }
        acc = warp_sum(acc);
        if (ln == 0) g_p2[((size_t)b * TDEC + s) * PRE + o] = fmaxf(acc + b2[o], 0.f);
    }
}

// ---------------- out/stop projection (warp per (col,b)) ----------------
__device__ __forceinline__ void outstop_warp(int col, int b, int sprev, int h1buf, int ln,
        const float* __restrict__ featW, const float* __restrict__ stopW,
        const float* __restrict__ stopb, float* __restrict__ out) {
    const float4* wr = (const float4*)((col < ODIM) ? (featW + (size_t)col * 1536) : stopW);
    const float4* h1p = (const float4*)(g_h1[h1buf] + b * DRNN);
    const float4* acp = (const float4*)(g_attc + ((size_t)(b * TDEC) + sprev) * DIN);
    float acc = 0.f;
    #pragma unroll
    for (int it = 0; it < 8; it++) {
        float4 wv = wr[ln + it * 32];
        float4 zv = h1p[ln + it * 32];
        acc += wv.x*zv.x + wv.y*zv.y + wv.z*zv.z + wv.w*zv.w;
    }
    #pragma unroll
    for (int it = 0; it < 4; it++) {
        float4 wv = wr[256 + ln + it * 32];
        float4 zv = acp[ln + it * 32];
        acc += wv.x*zv.x + wv.y*zv.y + wv.z*zv.z + wv.w*zv.w;
    }
    acc = warp_sum(acc);
    if (ln == 0) {
        if (col < ODIM) out[((size_t)(b * TDEC) + sprev) * ODIM + col] = acc;
        else            out[BB * TDEC * ODIM + b * TDEC + sprev] = acc + stopb[0];
    }
}

// ---------------- persistent decoder ----------------
__global__ __launch_bounds__(512) void decoder_persistent(
        const float* __restrict__ mem, const int* __restrict__ mlen,
        const float* __restrict__ Wq, const float* __restrict__ Wloc,
        const float* __restrict__ filt, const float* __restrict__ av,
        const float* __restrict__ ab,
        const float* __restrict__ Wi0, const float* __restrict__ Wh0,
        const float* __restrict__ bl0,
        const float* __restrict__ Wi1, const float* __restrict__ Wh1,
        const float* __restrict__ bl1,
        const float* __restrict__ featW, const float* __restrict__ stopW,
        const float* __restrict__ stopb, float* __restrict__ out)
{
    extern __shared__ __align__(16) float sm[];
    const int bid = blockIdx.x, tid = threadIdx.x;
    const int w = tid >> 5, ln = tid & 31;

    // loop-invariant attention constants (blocks 0..127 run the A phase)
    if (bid < 128) {
        float* Wl  = sm + OFF_ACON;          // [a*32+c]
        float* flt = sm + OFF_ACON + 4096;   // [c*31+k]
        float* vv  = sm + OFF_ACON + 5088;
        for (int i = tid; i < 4096; i += 512) Wl[i] = Wloc[i];
        for (int i = tid; i < 992; i += 512) flt[i] = filt[i];
        if (tid < 128) vv[tid] = av[tid];
    }
    __syncthreads();

    for (int s = 0; s <= TDEC; s++) {
        const int ep = s & 1;

        // ===== P1: blocks 0..127 do E(s-1) [FFMA2], then A(s) =====
        if (bid < 128) {
            if (s > 0) {
                // stage x transposed: xs[k][b], row stride 10 (8 batches + 2 pad)
                float* xs = sm;
                const float4* h0_4 = (const float4*)(g_h0[ep]);
                const float4* h1_4 = (const float4*)(g_h1[ep ^ 1]);
                for (int i = tid; i < 4096; i += 512) {
                    int b = i >> 9, o = i & 511;
                    float4 v = (o < 256) ? h0_4[b * 256 + o] : h1_4[b * 256 + (o - 256)];
                    int k = o * 4;
                    xs[(k    ) * 10 + b] = v.x;
                    xs[(k + 1) * 10 + b] = v.y;
                    xs[(k + 2) * 10 + b] = v.z;
                    xs[(k + 3) * 10 + b] = v.w;
                }
                __syncthreads();
                int jj = w >> 1, half = w & 1;
                int j = bid * 8 + jj;
                const float* wbase = half ? Wh1 : Wi1;
                const float* w0 = wbase + (size_t)(0 * 1024 + j) * 1024;
                const float* w1 = wbase + (size_t)(1 * 1024 + j) * 1024;
                const float* w2 = wbase + (size_t)(2 * 1024 + j) * 1024;
                const float* w3 = wbase + (size_t)(3 * 1024 + j) * 1024;
                const float* xbase = xs + (size_t)(half * 1024) * 10;
                unsigned long long acc2[4][4];
                #pragma unroll
                for (int g = 0; g < 4; g++)
                    #pragma unroll
                    for (int bp = 0; bp < 4; bp++) acc2[g][bp] = 0ull;
                #pragma unroll 4
                for (int kk = 0; kk < 32; kk++) {
                    int kl = kk * 32 + ln;
                    unsigned long long W0 = pack_dup(w0[kl]);
                    unsigned long long W1 = pack_dup(w1[kl]);
                    unsigned long long W2 = pack_dup(w2[kl]);
                    unsigned long long W3 = pack_dup(w3[kl]);
                    const float* xr = xbase + kl * 10;
                    unsigned long long X0 = *(const unsigned long long*)(xr    );
                    unsigned long long X1 = *(const unsigned long long*)(xr + 2);
                    unsigned long long X2 = *(const unsigned long long*)(xr + 4);
                    unsigned long long X3 = *(const unsigned long long*)(xr + 6);
                    fma2(acc2[0][0], W0, X0); fma2(acc2[0][1], W0, X1);
                    fma2(acc2[0][2], W0, X2); fma2(acc2[0][3], W0, X3);
                    fma2(acc2[1][0], W1, X0); fma2(acc2[1][1], W1, X1);
                    fma2(acc2[1][2], W1, X2); fma2(acc2[1][3], W1, X3);
                    fma2(acc2[2][0], W2, X0); fma2(acc2[2][1], W2, X1);
                    fma2(acc2[2][2], W2, X2); fma2(acc2[2][3], W2, X3);
                    fma2(acc2[3][0], W3, X0); fma2(acc2[3][1], W3, X1);
                    fma2(acc2[3][2], W3, X2); fma2(acc2[3][3], W3, X3);
                }
                float* P = sm + OFF_PART;
                #pragma unroll
                for (int g = 0; g < 4; g++)
                    #pragma unroll
                    for (int bp = 0; bp < 4; bp++) {
                        union { unsigned long long u; float2 f; } cv;
                        cv.u = acc2[g][bp];
                        float vlo = warp_sum(cv.f.x);
                        float vhi = warp_sum(cv.f.y);
                        if (ln == 0) {
                            P[((jj * 2 + half) * 4 + g) * 8 + bp * 2    ] = vlo;
                            P[((jj * 2 + half) * 4 + g) * 8 + bp * 2 + 1] = vhi;
                        }
                    }
                __syncthreads();
                if (tid < 64) {
                    int jj2 = tid >> 3, b = tid & 7, j2 = bid * 8 + jj2;
                    float gi = P[((jj2*2)*4+0)*8+b] + P[((jj2*2+1)*4+0)*8+b] + bl1[j2];
                    float gf = P[((jj2*2)*4+1)*8+b] + P[((jj2*2+1)*4+1)*8+b] + bl1[j2 + 1024];
                    float gg = P[((jj2*2)*4+2)*8+b] + P[((jj2*2+1)*4+2)*8+b] + bl1[j2 + 2048];
                    float go = P[((jj2*2)*4+3)*8+b] + P[((jj2*2+1)*4+3)*8+b] + bl1[j2 + 3072];
                    int idx = b * DRNN + j2;
                    float co = g_c1[ep ^ 1][idx], ho = g_h1[ep ^ 1][idx];
                    float cn = sigm(gf) * co + sigm(gi) * tanh_f(gg);
                    float hn = sigm(go) * tanh_f(cn);
                    g_c1[ep][idx] = 0.9f * cn + 0.1f * co;
                    g_h1[ep][idx] = 0.9f * hn + 0.1f * ho;
                }
            }
            if (s < TDEC) {
                // ---- A(s): attention energies, 128 blocks = (b, 32-t tile) ----
                __syncthreads();
                const int b = bid >> 4, t0 = (bid & 15) * 32;
                float* qs   = sm;            // 128
                float* part = sm + 128;      // 512
                float* fs   = sm + 640;      // 32*33 = 1056
                float* cum  = sm + 1696;     // 64
                float* eps  = sm + 1760;     // 512
                const float* Wl  = sm + OFF_ACON;
                const float* flt = sm + OFF_ACON + 4096;
                const float* vv  = sm + OFF_ACON + 5088;
                {
                    int a = tid & 127, qtr = tid >> 7;
                    float accq = 0.f;
                    #pragma unroll 4
                    for (int blk = qtr * 32; blk < qtr * 32 + 32; blk++)
                        accq += g_qp[blk * 1024 + b * 128 + a];
                    part[qtr * 128 + a] = accq;
                }
                if (tid < 64) {
                    int t = t0 - 15 + tid;
                    cum[tid] = (t >= 0 && t < TENC) ? g_attcum[b * TENC + t] : 0.f;
                }
                __syncthreads();
                if (tid < 128)
                    qs[tid] = part[tid] + part[128 + tid] + part[256 + tid] + part[384 + tid] + ab[tid];
                __syncthreads();
                #pragma unroll
                for (int hf = 0; hf < 2; hf++) {
                    int c = w + hf * 16;
                    float f = 0.f;
                    #pragma unroll
                    for (int k = 0; k < KF; k++) f += cum[ln + k] * flt[c * KF + k];
                    fs[ln * 33 + c] = f;
                }
                __syncthreads();
                float accA[8];
                #pragma unroll
                for (int i = 0; i < 8; i++) accA[i] = 0.f;
                #pragma unroll 4
                for (int c = 0; c < 32; c++) {
                    float fv = fs[ln * 33 + c];
                    #pragma unroll
                    for (int i = 0; i < 8; i++)
                        accA[i] += fv * Wl[(w * 8 + i) * 32 + c];
                }
                const float4* pmp = (const float4*)(g_pm + ((size_t)(b * TENC) + t0 + ln) * ATTN + w * 8);
                float ep_ = 0.f;
                #pragma unroll
                for (int v4 = 0; v4 < 2; v4++) {
                    float4 p = pmp[v4];
                    int a = w * 8 + v4 * 4;
                    ep_ += vv[a    ] * tanh_hw(p.x + accA[v4*4    ] + qs[a    ]);
                    ep_ += vv[a + 1] * tanh_hw(p.y + accA[v4*4 + 1] + qs[a + 1]);
                    ep_ += vv[a + 2] * tanh_hw(p.z + accA[v4*4 + 2] + qs[a + 2]);
                    ep_ += vv[a + 3] * tanh_hw(p.w + accA[v4*4 + 3] + qs[a + 3]);
                }
                eps[w * 32 + ln] = ep_;
                __syncthreads();
                if (w == 0) {
                    float e = 0.f;
                    #pragma unroll
                    for (int ww = 0; ww < 16; ww++) e += eps[ww * 32 + ln];
                    g_e[b * TENC + t0 + ln] = e;
                }
            }
        }
        gsync();

        // ===== P2: C_h(s) on blocks 0..127  ||  B(s) on blocks 128..143 =====
        if (s < TDEC && bid < 128) {
            // C_h = Wh0 . h0  (partials kept in smem for P3)
            float* xs = sm;   // [b][1024]
            float4* xs4 = (float4*)xs;
            const float4* h0_4 = (const float4*)(g_h0[ep]);
            for (int i = tid; i < 2048; i += 512) xs4[i] = h0_4[i];
            __syncthreads();
            int jj = w >> 1, half = w & 1;
            int j = bid * 8 + jj;
            const float4* wr0 = (const float4*)(Wh0 + (size_t)(0 * 1024 + j) * 1024 + half * 512);
            const float4* wr1 = (const float4*)(Wh0 + (size_t)(1 * 1024 + j) * 1024 + half * 512);
            const float4* wr2 = (const float4*)(Wh0 + (size_t)(2 * 1024 + j) * 1024 + half * 512);
            const float4* wr3 = (const float4*)(Wh0 + (size_t)(3 * 1024 + j) * 1024 + half * 512);
            float acc[4][8];
            #pragma unroll
            for (int g = 0; g < 4; g++)
                #pragma unroll
                for (int b = 0; b < 8; b++) acc[g][b] = 0.f;
            #pragma unroll 2
            for (int it = 0; it < 4; it++) {
                float4 wv0 = wr0[it * 32 + ln];
                float4 wv1 = wr1[it * 32 + ln];
                float4 wv2 = wr2[it * 32 + ln];
                float4 wv3 = wr3[it * 32 + ln];
                int xo = half * 512 + it * 128 + ln * 4;
                #pragma unroll
                for (int b = 0; b < 8; b++) {
                    float4 xv = *(const float4*)(xs + b * 1024 + xo);
                    acc[0][b] += wv0.x*xv.x + wv0.y*xv.y + wv0.z*xv.z + wv0.w*xv.w;
                    acc[1][b] += wv1.x*xv.x + wv1.y*xv.y + wv1.z*xv.z + wv1.w*xv.w;
                    acc[2][b] += wv2.x*xv.x + wv2.y*xv.y + wv2.z*xv.z + wv2.w*xv.w;
                    acc[3][b] += wv3.x*xv.x + wv3.y*xv.y + wv3.z*xv.z + wv3.w*xv.w;
                }
            }
            float* Pc = sm + OFF_CH;
            #pragma unroll
            for (int g = 0; g < 4; g++)
                #pragma unroll
                for (int b = 0; b < 8; b++) {
                    float v = warp_sum(acc[g][b]);
                    if (ln == 0) Pc[((jj * 2 + half) * 4 + g) * 8 + b] = v;
                }
        } else if (s < TDEC && bid >= 128 && bid < 144) {
            const int bb = bid - 128;
            const int b = bb >> 1, half = bb & 1;
            float* wsm  = sm;                     // 512
            float* red  = sm + 512;               // 16
            float4* ctx4 = (float4*)(sm + 528);   // 8 tg * 64 float4
            int len = mlen[b];
            const float* epv = g_e + b * TENC;
            float e0 = (tid < len) ? epv[tid] : -1e9f;
            float mx = e0;
            #pragma unroll
            for (int o = 16; o; o >>= 1) mx = fmaxf(mx, __shfl_xor_sync(0xffffffffu, mx, o));
            if (ln == 0) red[w] = mx;
            __syncthreads();
            mx = red[0];
            #pragma unroll
            for (int ww = 1; ww < 16; ww++) mx = fmaxf(mx, red[ww]);
            float x0 = __expf(e0 - mx);
            float sw = warp_sum(x0);
            __syncthreads();
            if (ln == 0) red[w] = sw;
            __syncthreads();
            float S = 0.f;
            #pragma unroll
            for (int ww = 0; ww < 16; ww++) S += red[ww];
            float inv = __fdividef(1.0f, S);
            wsm[tid] = x0 * inv;
            __syncthreads();
            int tg = tid >> 6, dl = tid & 63;
            const float4* mp4 = (const float4*)(mem + ((size_t)b * TENC) * DIN + half * 256) + dl;
            float4 a = {0.f, 0.f, 0.f, 0.f};
            #pragma unroll 4
            for (int t = tg * 64; t < tg * 64 + 64; t++) {
                float wv = wsm[t];
                float4 m = mp4[(size_t)t * 128];
                a.x += wv * m.x; a.y += wv * m.y; a.z += wv * m.z; a.w += wv * m.w;
            }
            ctx4[tg * 64 + dl] = a;
            __syncthreads();
            if (tid < 64) {
                float4 sa = ctx4[tid];
                #pragma unroll
                for (int tg2 = 1; tg2 < 8; tg2++) {
                    float4 v = ctx4[tg2 * 64 + tid];
                    sa.x += v.x; sa.y += v.y; sa.z += v.z; sa.w += v.w;
                }
                *(float4*)(g_attc + ((size_t)(b * TDEC) + s) * DIN + half * 256 + tid * 4) = sa;
            }
            if (half == 0) {
                float wv = wsm[tid];
                out[BB * TDEC * ODIM + BB * TDEC + ((size_t)(b * TDEC) + s) * TENC + tid] = wv;
                g_attcum[b * TENC + tid] += wv;
            }
        }
        gsync();

        // ===== P3: C_x(s)+gates+qp on blocks 0..127  ||  outstop(s-1) on 128..147 =====
        if (s < TDEC && bid < 128) {
            float* xs = sm;  // [b][768] = 8*192 float4
            float4* xs4 = (float4*)xs;
            for (int i = tid; i < 1536; i += 512) {
                int b = i / 192, o = i - b * 192;
                float4 v;
                if (o < 128) v = ((const float4*)(g_attc + ((size_t)(b * TDEC) + s) * DIN))[o];
                else         v = ((const float4*)(g_p2 + ((size_t)(b * TDEC) + s) * PRE))[o - 128];
                xs4[i] = v;
            }
            __syncthreads();
            int jj = w >> 1, half = w & 1;
            int j = bid * 8 + jj;
            const float4* wr0 = (const float4*)(Wi0 + (size_t)(0 * 1024 + j) * 768 + half * 384);
            const float4* wr1 = (const float4*)(Wi0 + (size_t)(1 * 1024 + j) * 768 + half * 384);
            const float4* wr2 = (const float4*)(Wi0 + (size_t)(2 * 1024 + j) * 768 + half * 384);
            const float4* wr3 = (const float4*)(Wi0 + (size_t)(3 * 1024 + j) * 768 + half * 384);
            float acc[4][8];
            #pragma unroll
            for (int g = 0; g < 4; g++)
                #pragma unroll
                for (int b = 0; b < 8; b++) acc[g][b] = 0.f;
            #pragma unroll
            for (int it = 0; it < 3; it++) {
                float4 wv0 = wr0[it * 32 + ln];
                float4 wv1 = wr1[it * 32 + ln];
                float4 wv2 = wr2[it * 32 + ln];
                float4 wv3 = wr3[it * 32 + ln];
                int xo = half * 384 + it * 128 + ln * 4;
                #pragma unroll
                for (int b = 0; b < 8; b++) {
                    float4 xv = *(const float4*)(xs + b * 768 + xo);
                    acc[0][b] += wv0.x*xv.x + wv0.y*xv.y + wv0.z*xv.z + wv0.w*xv.w;
                    acc[1][b] += wv1.x*xv.x + wv1.y*xv.y + wv1.z*xv.z + wv1.w*xv.w;
                    acc[2][b] += wv2.x*xv.x + wv2.y*xv.y + wv2.z*xv.z + wv2.w*xv.w;
                    acc[3][b] += wv3.x*xv.x + wv3.y*xv.y + wv3.z*xv.z + wv3.w*xv.w;
                }
            }
            float* P = sm + OFF_PART;
            float* h0s = sm + OFF_PART + 512;
            #pragma unroll
            for (int g = 0; g < 4; g++)
                #pragma unroll
                for (int b = 0; b < 8; b++) {
                    float v = warp_sum(acc[g][b]);
                    if (ln == 0) P[((jj * 2 + half) * 4 + g) * 8 + b] = v;
                }
            __syncthreads();
            if (tid < 64) {
                const float* Pc = sm + OFF_CH;
                int jj2 = tid >> 3, b = tid & 7, j2 = bid * 8 + jj2;
                float gi = P[((jj2*2)*4+0)*8+b] + P[((jj2*2+1)*4+0)*8+b]
                         + Pc[((jj2*2)*4+0)*8+b] + Pc[((jj2*2+1)*4+0)*8+b] + bl0[j2];
                float gf = P[((jj2*2)*4+1)*8+b] + P[((jj2*2+1)*4+1)*8+b]
                         + Pc[((jj2*2)*4+1)*8+b] + Pc[((jj2*2+1)*4+1)*8+b] + bl0[j2 + 1024];
                float gg = P[((jj2*2)*4+2)*8+b] + P[((jj2*2+1)*4+2)*8+b]
                         + Pc[((jj2*2)*4+2)*8+b] + Pc[((jj2*2+1)*4+2)*8+b] + bl0[j2 + 2048];
                float go = P[((jj2*2)*4+3)*8+b] + P[((jj2*2+1)*4+3)*8+b]
                         + Pc[((jj2*2)*4+3)*8+b] + Pc[((jj2*2+1)*4+3)*8+b] + bl0[j2 + 3072];
                int idx = b * DRNN + j2;
                float co = g_c0[ep][idx], ho = g_h0[ep][idx];
                float cn = sigm(gf) * co + sigm(gi) * tanh_f(gg);
                float hn = sigm(go) * tanh_f(cn);
                float hmix = 0.9f * hn + 0.1f * ho;
                g_c0[ep ^ 1][idx] = 0.9f * cn + 0.1f * co;
                g_h0[ep ^ 1][idx] = hmix;
                h0s[jj2 * 8 + b] = hmix;
            }
            __syncthreads();
            // deterministic q partials for step s+1
            if (tid < 128) {
                int a = tid;
                float4 wq1 = *(const float4*)(Wq + (size_t)a * DRNN + bid * 8);
                float4 wq2 = *(const float4*)(Wq + (size_t)a * DRNN + bid * 8 + 4);
                float* h0s2 = sm + OFF_PART + 512;
                #pragma unroll
                for (int b = 0; b < 8; b++) {
                    float sq = wq1.x*h0s2[0*8+b] + wq1.y*h0s2[1*8+b] + wq1.z*h0s2[2*8+b] + wq1.w*h0s2[3*8+b]
                             + wq2.x*h0s2[4*8+b] + wq2.y*h0s2[5*8+b] + wq2.z*h0s2[6*8+b] + wq2.w*h0s2[7*8+b];
                    g_qp[bid * 1024 + b * 128 + a] = sq;
                }
            }
        } else if (s > 0 && bid >= 128) {
            // out/stop for step s-1 on 20 side blocks
            #pragma unroll
            for (int r = 0; r < 3; r++) {
                int u = (bid - 128) * 16 + w + r * 320;
                if (u < (ODIM + 1) * BB)
                    outstop_warp(u >> 3, u & 7, s - 1, ep, ln, featW, stopW, stopb, out);
            }
        }
        if (s == TDEC) break;
        gsync();
    }
}

extern "C" void kernel_launch(void* const* d_in, const int* in_sizes, int n_in,
                              void* d_out, int out_size) {
    const float* mem   = (const float*)d_in[0];
    const int*   mlen  = (const int*)  d_in[1];
    const float* tgt   = (const float*)d_in[2];
    const float* Wmem  = (const float*)d_in[3];
    const float* Wq    = (const float*)d_in[4];
    const float* Wloc  = (const float*)d_in[5];
    const float* filt  = (const float*)d_in[6];
    const float* av    = (const float*)d_in[7];
    const float* ab    = (const float*)d_in[8];
    const float* pW1   = (const float*)d_in[9];
    const float* pb1   = (const float*)d_in[10];
    const float* pW2   = (const float*)d_in[11];
    const float* pb2   = (const float*)d_in[12];
    const float* Wi0   = (const float*)d_in[13];
    const float* Wh0   = (const float*)d_in[14];
    const float* bl0   = (const float*)d_in[15];
    const float* Wi1   = (const float*)d_in[16];
    const float* Wh1   = (const float*)d_in[17];
    const float* bl1   = (const float*)d_in[18];
    const float* featW = (const float*)d_in[19];
    const float* stopW = (const float*)d_in[20];
    const float* stopb = (const float*)d_in[21];
    float* out = (float*)d_out;

    static bool attr_set = false;
    if (!attr_set) {
        cudaFuncSetAttribute(decoder_persistent,
                             cudaFuncAttributeMaxDynamicSharedMemorySize,
                             SMEM_FLOATS * 4);
        attr_set = true;
    }

    init_kernel<<<512, 256>>>();
    pm_kernel<<<512, 256>>>(mem, Wmem);
    prenet_kernel<<<BB * TDEC, 256>>>(tgt, pW1, pb1, pW2, pb2);
    decoder_persistent<<<NBLK, 512, SMEM_FLOATS * 4>>>(
        mem, mlen, Wq, Wloc, filt, av, ab,
        Wi0, Wh0, bl0, Wi1, Wh1, bl1, featW, stopW, stopb, out);
}